// round 1
// baseline (speedup 1.0000x reference)
#include <cuda_runtime.h>
#include <math.h>

// Problem constants
#define B_    4
#define T_    2048
#define HID_  2048
#define NH    16
#define NKV   2
#define HD_   128
#define MROWS (B_ * T_)   // 8192

// Scratch (allocation-free rule: __device__ globals)
__device__ float g_q[(size_t)MROWS * HID_];        // 64 MB
__device__ float g_k[(size_t)MROWS * NKV * HD_];   // 8 MB
__device__ float g_v[(size_t)MROWS * NKV * HD_];   // 8 MB
__device__ float g_y[(size_t)MROWS * HID_];        // 64 MB

// ---------------------------------------------------------------------------
// SGEMM (NT): C[M,N] = A[M,K] * B[N,K]^T, both row-major / K-contiguous.
// 128x128 block tile, BK=16, 256 threads, 8x8 per thread.
// M % 128 == 0, N % 128 == 0, K % 16 == 0 assumed (holds for all calls).
// ---------------------------------------------------------------------------
#define BM 128
#define BN 128
#define BK 16

__global__ __launch_bounds__(256) void sgemm_nt(const float* __restrict__ A,
                                                const float* __restrict__ Bm,
                                                float* __restrict__ C,
                                                int M, int N, int K) {
    __shared__ float As[BK][BM];
    __shared__ float Bs[BK][BN];
    const int tid = threadIdx.x;
    const int bm = blockIdx.y * BM;
    const int bn = blockIdx.x * BN;
    const int tx = tid & 15;   // 0..15 -> cols
    const int ty = tid >> 4;   // 0..15 -> rows

    float acc[8][8] = {};

    for (int k0 = 0; k0 < K; k0 += BK) {
#pragma unroll
        for (int i = 0; i < 2; i++) {
            int idx = i * 256 + tid;        // 0..511
            int row = idx >> 2;             // 0..127
            int kc  = (idx & 3) << 2;       // 0,4,8,12
            float4 a = *(const float4*)(A + (size_t)(bm + row) * K + k0 + kc);
            As[kc + 0][row] = a.x; As[kc + 1][row] = a.y;
            As[kc + 2][row] = a.z; As[kc + 3][row] = a.w;
            float4 b = *(const float4*)(Bm + (size_t)(bn + row) * K + k0 + kc);
            Bs[kc + 0][row] = b.x; Bs[kc + 1][row] = b.y;
            Bs[kc + 2][row] = b.z; Bs[kc + 3][row] = b.w;
        }
        __syncthreads();
#pragma unroll
        for (int kk = 0; kk < BK; kk++) {
            float4 a0 = *(const float4*)&As[kk][ty * 8];
            float4 a1 = *(const float4*)&As[kk][ty * 8 + 4];
            float4 b0 = *(const float4*)&Bs[kk][tx * 8];
            float4 b1 = *(const float4*)&Bs[kk][tx * 8 + 4];
            float ar[8] = {a0.x, a0.y, a0.z, a0.w, a1.x, a1.y, a1.z, a1.w};
            float br[8] = {b0.x, b0.y, b0.z, b0.w, b1.x, b1.y, b1.z, b1.w};
#pragma unroll
            for (int j = 0; j < 8; j++)
#pragma unroll
                for (int i = 0; i < 8; i++)
                    acc[j][i] += ar[j] * br[i];
        }
        __syncthreads();
    }

#pragma unroll
    for (int j = 0; j < 8; j++) {
        size_t base = (size_t)(bm + ty * 8 + j) * N + bn + tx * 8;
        float4 c0 = {acc[j][0], acc[j][1], acc[j][2], acc[j][3]};
        float4 c1 = {acc[j][4], acc[j][5], acc[j][6], acc[j][7]};
        *(float4*)(C + base)     = c0;
        *(float4*)(C + base + 4) = c1;
    }
}

// ---------------------------------------------------------------------------
// Fused RoPE + RMSNorm. One warp per 128-elem head row (Q rows then K rows).
// RoPE: interleaved pairs (x[2i], x[2i+1]) rotated by (cos[i], sin[i]).
// RMSNorm over the 128-dim head AFTER rope (cos/sin are random, not unitary).
// ---------------------------------------------------------------------------
__global__ __launch_bounds__(256) void rope_rms(float* __restrict__ q,
                                                float* __restrict__ k,
                                                const float* __restrict__ cosp,
                                                const float* __restrict__ sinp) {
    int gw   = (blockIdx.x * 256 + threadIdx.x) >> 5;
    int lane = threadIdx.x & 31;
    const int QROWS = MROWS * NH;
    const int KROWS = MROWS * NKV;

    float* ptr;
    int t;
    if (gw < QROWS) {
        t = (gw >> 4) & (T_ - 1);           // bt = gw/16, t = bt % T
        ptr = q + (size_t)gw * HD_;
    } else {
        int r = gw - QROWS;
        if (r >= KROWS) return;
        t = (r >> 1) & (T_ - 1);
        ptr = k + (size_t)r * HD_;
    }

    float2 x0 = *(const float2*)(ptr + 2 * lane);
    float2 x1 = *(const float2*)(ptr + 2 * (lane + 32));
    float c0  = cosp[t * 64 + lane],      sn0 = sinp[t * 64 + lane];
    float c1  = cosp[t * 64 + lane + 32], sn1 = sinp[t * 64 + lane + 32];

    float o0r = x0.x * c0 - x0.y * sn0;
    float o0i = x0.x * sn0 + x0.y * c0;
    float o1r = x1.x * c1 - x1.y * sn1;
    float o1i = x1.x * sn1 + x1.y * c1;

    float ss = o0r * o0r + o0i * o0i + o1r * o1r + o1i * o1i;
#pragma unroll
    for (int off = 16; off > 0; off >>= 1)
        ss += __shfl_xor_sync(0xffffffffu, ss, off);
    float sc = rsqrtf(ss * (1.0f / 128.0f) + 1.1920929e-7f);

    float2 y0 = {o0r * sc, o0i * sc};
    float2 y1 = {o1r * sc, o1i * sc};
    *(float2*)(ptr + 2 * lane)        = y0;
    *(float2*)(ptr + 2 * (lane + 32)) = y1;
}

// ---------------------------------------------------------------------------
// Flash attention (fp32, causal, GQA 8:1). 64 queries x 64 keys per tile,
// HD=128. 256 threads: warp w owns query rows w*8..w*8+7; within the score
// phase lane owns keys {lane, lane+32}; within the PV phase lane owns output
// cols lane*4..lane*4+3. P staged through smem (written and read by the SAME
// warp -> only __syncwarp needed between S and PV).
// ---------------------------------------------------------------------------
#define FQS 132   // padded row stride (floats) for Qs/Ks/Vs (528B = 33*16B)
#define FPS 68    // padded row stride for Ps (272B = 17*16B)
#define FLASH_SMEM_BYTES ((3 * 64 * FQS + 64 * FPS) * 4)   // 118784

__global__ __launch_bounds__(256) void flash_attn(const float* __restrict__ Q,
                                                  const float* __restrict__ K,
                                                  const float* __restrict__ V,
                                                  float* __restrict__ Y) {
    extern __shared__ float sm[];
    float(*Qs)[FQS] = (float(*)[FQS])sm;
    float(*Ks)[FQS] = (float(*)[FQS])(sm + 64 * FQS);
    float(*Vs)[FQS] = (float(*)[FQS])(sm + 2 * 64 * FQS);
    float(*Ps)[FPS] = (float(*)[FPS])(sm + 3 * 64 * FQS);

    const int qt = blockIdx.x, h = blockIdx.y, b = blockIdx.z;
    const int g = h >> 3;                       // N_REP = 8
    const int tid = threadIdx.x, warp = tid >> 5, lane = tid & 31;
    const int q0 = qt * 64;
    const float scale = 0.08838834764831845f;   // 1/sqrt(128)

    // Load Q tile (scaled)
#pragma unroll
    for (int i = 0; i < 8; i++) {
        int idx = i * 256 + tid;
        int row = idx >> 5;
        int c   = (idx & 31) << 2;
        float4 qv = *(const float4*)(Q + ((size_t)((b * T_ + q0 + row) * NH + h)) * HD_ + c);
        qv.x *= scale; qv.y *= scale; qv.z *= scale; qv.w *= scale;
        *(float4*)&Qs[row][c] = qv;
    }

    float m[8], l[8], O[8][4];
#pragma unroll
    for (int j = 0; j < 8; j++) {
        m[j] = -INFINITY; l[j] = 0.0f;
        O[j][0] = O[j][1] = O[j][2] = O[j][3] = 0.0f;
    }
    const int r0 = warp * 8;
    const int oc = lane * 4;

    for (int kt = 0; kt <= qt; kt++) {
        __syncthreads();   // covers Q load (1st iter) + prior-tile Vs/Ks reads
#pragma unroll
        for (int i = 0; i < 8; i++) {
            int idx = i * 256 + tid;
            int row = idx >> 5;
            int c   = (idx & 31) << 2;
            size_t base = ((size_t)((b * T_ + kt * 64 + row) * NKV + g)) * HD_ + c;
            *(float4*)&Ks[row][c] = *(const float4*)(K + base);
            *(float4*)&Vs[row][c] = *(const float4*)(V + base);
        }
        __syncthreads();

        // Scores: lane computes 8 rows x keys {lane, lane+32}
        float s0[8] = {}, s1[8] = {};
#pragma unroll 4
        for (int kk = 0; kk < 128; kk += 4) {
            float4 ka = *(const float4*)&Ks[lane][kk];
            float4 kb = *(const float4*)&Ks[lane + 32][kk];
#pragma unroll
            for (int j = 0; j < 8; j++) {
                float4 qv = *(const float4*)&Qs[r0 + j][kk];
                s0[j] += qv.x * ka.x + qv.y * ka.y + qv.z * ka.z + qv.w * ka.w;
                s1[j] += qv.x * kb.x + qv.y * kb.y + qv.z * kb.z + qv.w * kb.w;
            }
        }

        if (kt == qt) {   // diagonal tile: mask key_rel > row_rel
#pragma unroll
            for (int j = 0; j < 8; j++) {
                int qi = r0 + j;
                if (lane > qi)      s0[j] = -INFINITY;
                if (lane + 32 > qi) s1[j] = -INFINITY;
            }
        }

        // Online softmax per row (warp-collective)
#pragma unroll
        for (int j = 0; j < 8; j++) {
            float mx = fmaxf(s0[j], s1[j]);
#pragma unroll
            for (int off = 16; off > 0; off >>= 1)
                mx = fmaxf(mx, __shfl_xor_sync(0xffffffffu, mx, off));
            float mn = fmaxf(m[j], mx);
            float a  = __expf(m[j] - mn);
            m[j] = mn;
            float p0 = __expf(s0[j] - mn);
            float p1 = __expf(s1[j] - mn);
            float ps = p0 + p1;
#pragma unroll
            for (int off = 16; off > 0; off >>= 1)
                ps += __shfl_xor_sync(0xffffffffu, ps, off);
            l[j] = l[j] * a + ps;
            O[j][0] *= a; O[j][1] *= a; O[j][2] *= a; O[j][3] *= a;
            Ps[r0 + j][lane]      = p0;
            Ps[r0 + j][lane + 32] = p1;
        }
        __syncwarp();

        // PV: O[j][0..3] += sum_s P[j][s] * V[s][oc..oc+3]
#pragma unroll 4
        for (int s2 = 0; s2 < 64; s2 += 4) {
            float4 v0 = *(const float4*)&Vs[s2 + 0][oc];
            float4 v1 = *(const float4*)&Vs[s2 + 1][oc];
            float4 v2 = *(const float4*)&Vs[s2 + 2][oc];
            float4 v3 = *(const float4*)&Vs[s2 + 3][oc];
#pragma unroll
            for (int j = 0; j < 8; j++) {
                float4 p = *(const float4*)&Ps[r0 + j][s2];
                O[j][0] += p.x * v0.x + p.y * v1.x + p.z * v2.x + p.w * v3.x;
                O[j][1] += p.x * v0.y + p.y * v1.y + p.z * v2.y + p.w * v3.y;
                O[j][2] += p.x * v0.z + p.y * v1.z + p.z * v2.z + p.w * v3.z;
                O[j][3] += p.x * v0.w + p.y * v1.w + p.z * v2.w + p.w * v3.w;
            }
        }
    }

    // Epilogue: normalize and store (layout matches Q: [b, t, head, hd])
#pragma unroll
    for (int j = 0; j < 8; j++) {
        float inv = 1.0f / l[j];
        float4 o = {O[j][0] * inv, O[j][1] * inv, O[j][2] * inv, O[j][3] * inv};
        *(float4*)(Y + ((size_t)((b * T_ + q0 + r0 + j) * NH + h)) * HD_ + oc) = o;
    }
}

// ---------------------------------------------------------------------------
// Launch
// ---------------------------------------------------------------------------
extern "C" void kernel_launch(void* const* d_in, const int* in_sizes, int n_in,
                              void* d_out, int out_size) {
    const float* x    = (const float*)d_in[0];
    const float* cosp = (const float*)d_in[1];
    const float* sinp = (const float*)d_in[2];
    const float* Wq   = (const float*)d_in[3];
    const float* Wk   = (const float*)d_in[4];
    const float* Wv   = (const float*)d_in[5];
    const float* Wo   = (const float*)d_in[6];
    float* out = (float*)d_out;

    float *q, *k, *v, *y;
    cudaGetSymbolAddress((void**)&q, g_q);
    cudaGetSymbolAddress((void**)&k, g_k);
    cudaGetSymbolAddress((void**)&v, g_v);
    cudaGetSymbolAddress((void**)&y, g_y);

    cudaFuncSetAttribute(flash_attn, cudaFuncAttributeMaxDynamicSharedMemorySize,
                         FLASH_SMEM_BYTES);

    dim3 blk(256);
    // QKV projections
    sgemm_nt<<<dim3(HID_ / BN, MROWS / BM), blk>>>(x, Wq, q, MROWS, HID_, HID_);
    sgemm_nt<<<dim3((NKV * HD_) / BN, MROWS / BM), blk>>>(x, Wk, k, MROWS, NKV * HD_, HID_);
    sgemm_nt<<<dim3((NKV * HD_) / BN, MROWS / BM), blk>>>(x, Wv, v, MROWS, NKV * HD_, HID_);
    // RoPE + RMSNorm on Q and K
    rope_rms<<<(MROWS * (NH + NKV)) / 8, blk>>>(q, k, cosp, sinp);
    // Causal GQA flash attention
    flash_attn<<<dim3(T_ / 64, NH, B_), blk, FLASH_SMEM_BYTES>>>(q, k, v, y);
    // Output projection
    sgemm_nt<<<dim3(HID_ / BN, MROWS / BM), blk>>>(y, Wo, out, MROWS, HID_, HID_);
}

// round 2
// speedup vs baseline: 1.7525x; 1.7525x over previous
#include <cuda_runtime.h>
#include <math.h>
#include <stdint.h>

// Problem constants
#define B_    4
#define T_    2048
#define HID_  2048
#define NH    16
#define NKV   2
#define HD_   128
#define MROWS (B_ * T_)   // 8192

// Scratch (allocation-free rule: __device__ globals)
__device__ float g_q[(size_t)MROWS * HID_];        // 64 MB
__device__ float g_k[(size_t)MROWS * NKV * HD_];   // 8 MB
__device__ float g_v[(size_t)MROWS * NKV * HD_];   // 8 MB
__device__ float g_y[(size_t)MROWS * HID_];        // 64 MB

// ---------------------------------------------------------------------------
// TF32 tensor-core GEMM (NT): C[M,N] = A[M,K] * B[N,K]^T, row-major.
// 128x128x32 block tile, 256 threads = 8 warps, warp tile 64x32 via
// mma.sync.m16n8k8.tf32. Inputs rounded to tf32 with cvt.rna at smem store.
// smem row stride 36 floats: fragment reads hit banks 4*gid+tig (conflict-
// free), 144B rows keep STS.128 16B-aligned.
// Requires M%128==0, N%128==0, K%32==0 (holds for all calls here).
// ---------------------------------------------------------------------------
#define SA 36

__device__ __forceinline__ uint32_t f2tf32(float f) {
    uint32_t u;
    asm("cvt.rna.tf32.f32 %0, %1;" : "=r"(u) : "f"(f));
    return u;
}

__device__ __forceinline__ void mma_tf32(float c[4],
                                         uint32_t a0, uint32_t a1, uint32_t a2, uint32_t a3,
                                         uint32_t b0, uint32_t b1) {
    asm volatile(
        "mma.sync.aligned.m16n8k8.row.col.f32.tf32.tf32.f32 "
        "{%0,%1,%2,%3}, {%4,%5,%6,%7}, {%8,%9}, {%0,%1,%2,%3};"
        : "+f"(c[0]), "+f"(c[1]), "+f"(c[2]), "+f"(c[3])
        : "r"(a0), "r"(a1), "r"(a2), "r"(a3), "r"(b0), "r"(b1));
}

__global__ __launch_bounds__(256) void tf32_gemm_nt(const float* __restrict__ A,
                                                    const float* __restrict__ Bm,
                                                    float* __restrict__ C,
                                                    int M, int N, int K) {
    __shared__ __align__(16) uint32_t As[128 * SA];
    __shared__ __align__(16) uint32_t Bs[128 * SA];

    const int tid  = threadIdx.x;
    const int lane = tid & 31, warp = tid >> 5;
    const int gid  = lane >> 2, tig = lane & 3;
    const int wm   = (warp >> 2) * 64;   // warp m-offset (0 or 64)
    const int wn   = (warp & 3) * 32;    // warp n-offset (0..96)
    const int bm   = blockIdx.y * 128;
    const int bn   = blockIdx.x * 128;

    float acc[4][4][4] = {};

    float4 pa[4], pb[4];
#pragma unroll
    for (int i = 0; i < 4; i++) {            // prologue gmem load (k0 = 0)
        int idx = i * 256 + tid;
        int row = idx >> 3, kc = (idx & 7) << 2;
        pa[i] = *(const float4*)(A  + (size_t)(bm + row) * K + kc);
        pb[i] = *(const float4*)(Bm + (size_t)(bn + row) * K + kc);
    }

    for (int k0 = 0; k0 < K; k0 += 32) {
        __syncthreads();
#pragma unroll
        for (int i = 0; i < 4; i++) {        // cvt.rna -> STS.128
            int idx = i * 256 + tid;
            int row = idx >> 3, kc = (idx & 7) << 2;
            uint4 ua = {f2tf32(pa[i].x), f2tf32(pa[i].y), f2tf32(pa[i].z), f2tf32(pa[i].w)};
            uint4 ub = {f2tf32(pb[i].x), f2tf32(pb[i].y), f2tf32(pb[i].z), f2tf32(pb[i].w)};
            *(uint4*)&As[row * SA + kc] = ua;
            *(uint4*)&Bs[row * SA + kc] = ub;
        }
        __syncthreads();

        if (k0 + 32 < K) {                   // prefetch next tile (overlaps MMA)
#pragma unroll
            for (int i = 0; i < 4; i++) {
                int idx = i * 256 + tid;
                int row = idx >> 3, kc = (idx & 7) << 2;
                pa[i] = *(const float4*)(A  + (size_t)(bm + row) * K + k0 + 32 + kc);
                pb[i] = *(const float4*)(Bm + (size_t)(bn + row) * K + k0 + 32 + kc);
            }
        }

#pragma unroll
        for (int kk = 0; kk < 32; kk += 8) {
            uint32_t af[4][4], bf[4][2];
#pragma unroll
            for (int mi = 0; mi < 4; mi++) {
                int mb = wm + mi * 16 + gid;
                af[mi][0] = As[mb * SA + kk + tig];
                af[mi][1] = As[(mb + 8) * SA + kk + tig];
                af[mi][2] = As[mb * SA + kk + tig + 4];
                af[mi][3] = As[(mb + 8) * SA + kk + tig + 4];
            }
#pragma unroll
            for (int ni = 0; ni < 4; ni++) {
                int nb = wn + ni * 8 + gid;
                bf[ni][0] = Bs[nb * SA + kk + tig];
                bf[ni][1] = Bs[nb * SA + kk + tig + 4];
            }
#pragma unroll
            for (int mi = 0; mi < 4; mi++)
#pragma unroll
                for (int ni = 0; ni < 4; ni++)
                    mma_tf32(acc[mi][ni], af[mi][0], af[mi][1], af[mi][2], af[mi][3],
                             bf[ni][0], bf[ni][1]);
        }
    }

#pragma unroll
    for (int mi = 0; mi < 4; mi++)
#pragma unroll
        for (int ni = 0; ni < 4; ni++) {
            int row = bm + wm + mi * 16 + gid;
            int col = bn + wn + ni * 8 + 2 * tig;
            float2 lo = {acc[mi][ni][0], acc[mi][ni][1]};
            float2 hi = {acc[mi][ni][2], acc[mi][ni][3]};
            *(float2*)(C + (size_t)row * N + col)       = lo;
            *(float2*)(C + (size_t)(row + 8) * N + col) = hi;
        }
}

// ---------------------------------------------------------------------------
// Fused RoPE + RMSNorm. One warp per 128-elem head row (Q rows then K rows).
// ---------------------------------------------------------------------------
__global__ __launch_bounds__(256) void rope_rms(float* __restrict__ q,
                                                float* __restrict__ k,
                                                const float* __restrict__ cosp,
                                                const float* __restrict__ sinp) {
    int gw   = (blockIdx.x * 256 + threadIdx.x) >> 5;
    int lane = threadIdx.x & 31;
    const int QROWS = MROWS * NH;
    const int KROWS = MROWS * NKV;

    float* ptr;
    int t;
    if (gw < QROWS) {
        t = (gw >> 4) & (T_ - 1);
        ptr = q + (size_t)gw * HD_;
    } else {
        int r = gw - QROWS;
        if (r >= KROWS) return;
        t = (r >> 1) & (T_ - 1);
        ptr = k + (size_t)r * HD_;
    }

    float2 x0 = *(const float2*)(ptr + 2 * lane);
    float2 x1 = *(const float2*)(ptr + 2 * (lane + 32));
    float c0  = cosp[t * 64 + lane],      sn0 = sinp[t * 64 + lane];
    float c1  = cosp[t * 64 + lane + 32], sn1 = sinp[t * 64 + lane + 32];

    float o0r = x0.x * c0 - x0.y * sn0;
    float o0i = x0.x * sn0 + x0.y * c0;
    float o1r = x1.x * c1 - x1.y * sn1;
    float o1i = x1.x * sn1 + x1.y * c1;

    float ss = o0r * o0r + o0i * o0i + o1r * o1r + o1i * o1i;
#pragma unroll
    for (int off = 16; off > 0; off >>= 1)
        ss += __shfl_xor_sync(0xffffffffu, ss, off);
    float sc = rsqrtf(ss * (1.0f / 128.0f) + 1.1920929e-7f);

    float2 y0 = {o0r * sc, o0i * sc};
    float2 y1 = {o1r * sc, o1i * sc};
    *(float2*)(ptr + 2 * lane)        = y0;
    *(float2*)(ptr + 2 * (lane + 32)) = y1;
}

// ---------------------------------------------------------------------------
// Flash attention (fp32, causal, GQA 8:1). 64x64 tiles, HD=128, 256 threads.
// ---------------------------------------------------------------------------
#define FQS 132
#define FPS 68
#define FLASH_SMEM_BYTES ((3 * 64 * FQS + 64 * FPS) * 4)   // 118784

__global__ __launch_bounds__(256) void flash_attn(const float* __restrict__ Q,
                                                  const float* __restrict__ K,
                                                  const float* __restrict__ V,
                                                  float* __restrict__ Y) {
    extern __shared__ float sm[];
    float(*Qs)[FQS] = (float(*)[FQS])sm;
    float(*Ks)[FQS] = (float(*)[FQS])(sm + 64 * FQS);
    float(*Vs)[FQS] = (float(*)[FQS])(sm + 2 * 64 * FQS);
    float(*Ps)[FPS] = (float(*)[FPS])(sm + 3 * 64 * FQS);

    const int qt = blockIdx.x, h = blockIdx.y, b = blockIdx.z;
    const int g = h >> 3;
    const int tid = threadIdx.x, warp = tid >> 5, lane = tid & 31;
    const int q0 = qt * 64;
    const float scale = 0.08838834764831845f;

#pragma unroll
    for (int i = 0; i < 8; i++) {
        int idx = i * 256 + tid;
        int row = idx >> 5;
        int c   = (idx & 31) << 2;
        float4 qv = *(const float4*)(Q + ((size_t)((b * T_ + q0 + row) * NH + h)) * HD_ + c);
        qv.x *= scale; qv.y *= scale; qv.z *= scale; qv.w *= scale;
        *(float4*)&Qs[row][c] = qv;
    }

    float m[8], l[8], O[8][4];
#pragma unroll
    for (int j = 0; j < 8; j++) {
        m[j] = -INFINITY; l[j] = 0.0f;
        O[j][0] = O[j][1] = O[j][2] = O[j][3] = 0.0f;
    }
    const int r0 = warp * 8;
    const int oc = lane * 4;

    for (int kt = 0; kt <= qt; kt++) {
        __syncthreads();
#pragma unroll
        for (int i = 0; i < 8; i++) {
            int idx = i * 256 + tid;
            int row = idx >> 5;
            int c   = (idx & 31) << 2;
            size_t base = ((size_t)((b * T_ + kt * 64 + row) * NKV + g)) * HD_ + c;
            *(float4*)&Ks[row][c] = *(const float4*)(K + base);
            *(float4*)&Vs[row][c] = *(const float4*)(V + base);
        }
        __syncthreads();

        float s0[8] = {}, s1[8] = {};
#pragma unroll 4
        for (int kk = 0; kk < 128; kk += 4) {
            float4 ka = *(const float4*)&Ks[lane][kk];
            float4 kb = *(const float4*)&Ks[lane + 32][kk];
#pragma unroll
            for (int j = 0; j < 8; j++) {
                float4 qv = *(const float4*)&Qs[r0 + j][kk];
                s0[j] += qv.x * ka.x + qv.y * ka.y + qv.z * ka.z + qv.w * ka.w;
                s1[j] += qv.x * kb.x + qv.y * kb.y + qv.z * kb.z + qv.w * kb.w;
            }
        }

        if (kt == qt) {
#pragma unroll
            for (int j = 0; j < 8; j++) {
                int qi = r0 + j;
                if (lane > qi)      s0[j] = -INFINITY;
                if (lane + 32 > qi) s1[j] = -INFINITY;
            }
        }

#pragma unroll
        for (int j = 0; j < 8; j++) {
            float mx = fmaxf(s0[j], s1[j]);
#pragma unroll
            for (int off = 16; off > 0; off >>= 1)
                mx = fmaxf(mx, __shfl_xor_sync(0xffffffffu, mx, off));
            float mn = fmaxf(m[j], mx);
            float a  = __expf(m[j] - mn);
            m[j] = mn;
            float p0 = __expf(s0[j] - mn);
            float p1 = __expf(s1[j] - mn);
            float ps = p0 + p1;
#pragma unroll
            for (int off = 16; off > 0; off >>= 1)
                ps += __shfl_xor_sync(0xffffffffu, ps, off);
            l[j] = l[j] * a + ps;
            O[j][0] *= a; O[j][1] *= a; O[j][2] *= a; O[j][3] *= a;
            Ps[r0 + j][lane]      = p0;
            Ps[r0 + j][lane + 32] = p1;
        }
        __syncwarp();

#pragma unroll 4
        for (int s2 = 0; s2 < 64; s2 += 4) {
            float4 v0 = *(const float4*)&Vs[s2 + 0][oc];
            float4 v1 = *(const float4*)&Vs[s2 + 1][oc];
            float4 v2 = *(const float4*)&Vs[s2 + 2][oc];
            float4 v3 = *(const float4*)&Vs[s2 + 3][oc];
#pragma unroll
            for (int j = 0; j < 8; j++) {
                float4 p = *(const float4*)&Ps[r0 + j][s2];
                O[j][0] += p.x * v0.x + p.y * v1.x + p.z * v2.x + p.w * v3.x;
                O[j][1] += p.x * v0.y + p.y * v1.y + p.z * v2.y + p.w * v3.y;
                O[j][2] += p.x * v0.z + p.y * v1.z + p.z * v2.z + p.w * v3.z;
                O[j][3] += p.x * v0.w + p.y * v1.w + p.z * v2.w + p.w * v3.w;
            }
        }
    }

#pragma unroll
    for (int j = 0; j < 8; j++) {
        float inv = 1.0f / l[j];
        float4 o = {O[j][0] * inv, O[j][1] * inv, O[j][2] * inv, O[j][3] * inv};
        *(float4*)(Y + ((size_t)((b * T_ + q0 + r0 + j) * NH + h)) * HD_ + oc) = o;
    }
}

// ---------------------------------------------------------------------------
// Launch
// ---------------------------------------------------------------------------
extern "C" void kernel_launch(void* const* d_in, const int* in_sizes, int n_in,
                              void* d_out, int out_size) {
    const float* x    = (const float*)d_in[0];
    const float* cosp = (const float*)d_in[1];
    const float* sinp = (const float*)d_in[2];
    const float* Wq   = (const float*)d_in[3];
    const float* Wk   = (const float*)d_in[4];
    const float* Wv   = (const float*)d_in[5];
    const float* Wo   = (const float*)d_in[6];
    float* out = (float*)d_out;

    float *q, *k, *v, *y;
    cudaGetSymbolAddress((void**)&q, g_q);
    cudaGetSymbolAddress((void**)&k, g_k);
    cudaGetSymbolAddress((void**)&v, g_v);
    cudaGetSymbolAddress((void**)&y, g_y);

    cudaFuncSetAttribute(flash_attn, cudaFuncAttributeMaxDynamicSharedMemorySize,
                         FLASH_SMEM_BYTES);

    dim3 blk(256);
    // QKV projections (TF32 tensor cores)
    tf32_gemm_nt<<<dim3(HID_ / 128, MROWS / 128), blk>>>(x, Wq, q, MROWS, HID_, HID_);
    tf32_gemm_nt<<<dim3((NKV * HD_) / 128, MROWS / 128), blk>>>(x, Wk, k, MROWS, NKV * HD_, HID_);
    tf32_gemm_nt<<<dim3((NKV * HD_) / 128, MROWS / 128), blk>>>(x, Wv, v, MROWS, NKV * HD_, HID_);
    // RoPE + RMSNorm on Q and K
    rope_rms<<<(MROWS * (NH + NKV)) / 8, blk>>>(q, k, cosp, sinp);
    // Causal GQA flash attention (fp32)
    flash_attn<<<dim3(T_ / 64, NH, B_), blk, FLASH_SMEM_BYTES>>>(q, k, v, y);
    // Output projection (TF32 tensor cores)
    tf32_gemm_nt<<<dim3(HID_ / 128, MROWS / 128), blk>>>(y, Wo, out, MROWS, HID_, HID_);
}

// round 3
// speedup vs baseline: 3.6040x; 2.0564x over previous
#include <cuda_runtime.h>
#include <math.h>
#include <stdint.h>

// Problem constants
#define B_    4
#define T_    2048
#define HID_  2048
#define NH    16
#define NKV   2
#define HD_   128
#define MROWS (B_ * T_)   // 8192

// Scratch (allocation-free rule: __device__ globals)
__device__ float g_q[(size_t)MROWS * HID_];        // 64 MB
__device__ float g_k[(size_t)MROWS * NKV * HD_];   // 8 MB
__device__ float g_v[(size_t)MROWS * NKV * HD_];   // 8 MB
__device__ float g_y[(size_t)MROWS * HID_];        // 64 MB

__device__ __forceinline__ uint32_t f2tf32(float f) {
    uint32_t u;
    asm("cvt.rna.tf32.f32 %0, %1;" : "=r"(u) : "f"(f));
    return u;
}

__device__ __forceinline__ void mma_tf32(float c[4],
                                         uint32_t a0, uint32_t a1, uint32_t a2, uint32_t a3,
                                         uint32_t b0, uint32_t b1) {
    asm volatile(
        "mma.sync.aligned.m16n8k8.row.col.f32.tf32.tf32.f32 "
        "{%0,%1,%2,%3}, {%4,%5,%6,%7}, {%8,%9}, {%0,%1,%2,%3};"
        : "+f"(c[0]), "+f"(c[1]), "+f"(c[2]), "+f"(c[3])
        : "r"(a0), "r"(a1), "r"(a2), "r"(a3), "r"(b0), "r"(b1));
}

// ---------------------------------------------------------------------------
// TF32 tensor-core GEMM (NT): C[M,N] = A[M,K] * B[N,K]^T, row-major.
// 128x128x32 block tile, 256 threads, warp tile 64x32. (unchanged from R2)
// ---------------------------------------------------------------------------
#define SA 36

__global__ __launch_bounds__(256) void tf32_gemm_nt(const float* __restrict__ A,
                                                    const float* __restrict__ Bm,
                                                    float* __restrict__ C,
                                                    int M, int N, int K) {
    __shared__ __align__(16) uint32_t As[128 * SA];
    __shared__ __align__(16) uint32_t Bs[128 * SA];

    const int tid  = threadIdx.x;
    const int lane = tid & 31, warp = tid >> 5;
    const int gid  = lane >> 2, tig = lane & 3;
    const int wm   = (warp >> 2) * 64;
    const int wn   = (warp & 3) * 32;
    const int bm   = blockIdx.y * 128;
    const int bn   = blockIdx.x * 128;

    float acc[4][4][4] = {};

    float4 pa[4], pb[4];
#pragma unroll
    for (int i = 0; i < 4; i++) {
        int idx = i * 256 + tid;
        int row = idx >> 3, kc = (idx & 7) << 2;
        pa[i] = *(const float4*)(A  + (size_t)(bm + row) * K + kc);
        pb[i] = *(const float4*)(Bm + (size_t)(bn + row) * K + kc);
    }

    for (int k0 = 0; k0 < K; k0 += 32) {
        __syncthreads();
#pragma unroll
        for (int i = 0; i < 4; i++) {
            int idx = i * 256 + tid;
            int row = idx >> 3, kc = (idx & 7) << 2;
            uint4 ua = {f2tf32(pa[i].x), f2tf32(pa[i].y), f2tf32(pa[i].z), f2tf32(pa[i].w)};
            uint4 ub = {f2tf32(pb[i].x), f2tf32(pb[i].y), f2tf32(pb[i].z), f2tf32(pb[i].w)};
            *(uint4*)&As[row * SA + kc] = ua;
            *(uint4*)&Bs[row * SA + kc] = ub;
        }
        __syncthreads();

        if (k0 + 32 < K) {
#pragma unroll
            for (int i = 0; i < 4; i++) {
                int idx = i * 256 + tid;
                int row = idx >> 3, kc = (idx & 7) << 2;
                pa[i] = *(const float4*)(A  + (size_t)(bm + row) * K + k0 + 32 + kc);
                pb[i] = *(const float4*)(Bm + (size_t)(bn + row) * K + k0 + 32 + kc);
            }
        }

#pragma unroll
        for (int kk = 0; kk < 32; kk += 8) {
            uint32_t af[4][4], bf[4][2];
#pragma unroll
            for (int mi = 0; mi < 4; mi++) {
                int mb = wm + mi * 16 + gid;
                af[mi][0] = As[mb * SA + kk + tig];
                af[mi][1] = As[(mb + 8) * SA + kk + tig];
                af[mi][2] = As[mb * SA + kk + tig + 4];
                af[mi][3] = As[(mb + 8) * SA + kk + tig + 4];
            }
#pragma unroll
            for (int ni = 0; ni < 4; ni++) {
                int nb = wn + ni * 8 + gid;
                bf[ni][0] = Bs[nb * SA + kk + tig];
                bf[ni][1] = Bs[nb * SA + kk + tig + 4];
            }
#pragma unroll
            for (int mi = 0; mi < 4; mi++)
#pragma unroll
                for (int ni = 0; ni < 4; ni++)
                    mma_tf32(acc[mi][ni], af[mi][0], af[mi][1], af[mi][2], af[mi][3],
                             bf[ni][0], bf[ni][1]);
        }
    }

#pragma unroll
    for (int mi = 0; mi < 4; mi++)
#pragma unroll
        for (int ni = 0; ni < 4; ni++) {
            int row = bm + wm + mi * 16 + gid;
            int col = bn + wn + ni * 8 + 2 * tig;
            float2 lo = {acc[mi][ni][0], acc[mi][ni][1]};
            float2 hi = {acc[mi][ni][2], acc[mi][ni][3]};
            *(float2*)(C + (size_t)row * N + col)       = lo;
            *(float2*)(C + (size_t)(row + 8) * N + col) = hi;
        }
}

// ---------------------------------------------------------------------------
// Fused RoPE + RMSNorm. One warp per 128-elem head row (Q rows then K rows).
// ---------------------------------------------------------------------------
__global__ __launch_bounds__(256) void rope_rms(float* __restrict__ q,
                                                float* __restrict__ k,
                                                const float* __restrict__ cosp,
                                                const float* __restrict__ sinp) {
    int gw   = (blockIdx.x * 256 + threadIdx.x) >> 5;
    int lane = threadIdx.x & 31;
    const int QROWS = MROWS * NH;
    const int KROWS = MROWS * NKV;

    float* ptr;
    int t;
    if (gw < QROWS) {
        t = (gw >> 4) & (T_ - 1);
        ptr = q + (size_t)gw * HD_;
    } else {
        int r = gw - QROWS;
        if (r >= KROWS) return;
        t = (r >> 1) & (T_ - 1);
        ptr = k + (size_t)r * HD_;
    }

    float2 x0 = *(const float2*)(ptr + 2 * lane);
    float2 x1 = *(const float2*)(ptr + 2 * (lane + 32));
    float c0  = cosp[t * 64 + lane],      sn0 = sinp[t * 64 + lane];
    float c1  = cosp[t * 64 + lane + 32], sn1 = sinp[t * 64 + lane + 32];

    float o0r = x0.x * c0 - x0.y * sn0;
    float o0i = x0.x * sn0 + x0.y * c0;
    float o1r = x1.x * c1 - x1.y * sn1;
    float o1i = x1.x * sn1 + x1.y * c1;

    float ss = o0r * o0r + o0i * o0i + o1r * o1r + o1i * o1i;
#pragma unroll
    for (int off = 16; off > 0; off >>= 1)
        ss += __shfl_xor_sync(0xffffffffu, ss, off);
    float sc = rsqrtf(ss * (1.0f / 128.0f) + 1.1920929e-7f);

    float2 y0 = {o0r * sc, o0i * sc};
    float2 y1 = {o1r * sc, o1i * sc};
    *(float2*)(ptr + 2 * lane)        = y0;
    *(float2*)(ptr + 2 * (lane + 32)) = y1;
}

// ---------------------------------------------------------------------------
// TF32 tensor-core flash attention (causal, GQA 8:1).
// 128 q-rows x 64 kv per block, HD=128, 256 threads = 8 warps.
// Warp w owns q rows w*16..w*16+15 (one m16 MMA row-tile).
// QK^T: mma row.col (Q row-major, K as [kv, hd] -> B col-major).
// Softmax fp32 in registers (quad shuffles), P restaged via smem as tf32.
// PV: mma row.col (P row-major, V as [kv, hd] read column-wise -> B col-major).
// smem strides picked for conflict-free fragment LDS:
//   Q/K/P stride % 32 == 4 (a/b frags: bank = 4*gid + tig),
//   V stride % 32 == 8 (b frags: bank = 8*tig + gid).
// ---------------------------------------------------------------------------
#define BQ   128
#define BKV  64
#define QSTR 132
#define KSTR 132
#define VSTR 136
#define PSTR 68
#define OFF_K (BQ * QSTR)                    // 16896
#define OFF_V (OFF_K + BKV * KSTR)           // 25344
#define OFF_P (OFF_V + BKV * VSTR)           // 34048
#define FLASH_SMEM_BYTES ((OFF_P + BQ * PSTR) * 4)   // 171008

__global__ __launch_bounds__(256) void flash_tf32(const float* __restrict__ Q,
                                                  const float* __restrict__ K,
                                                  const float* __restrict__ V,
                                                  float* __restrict__ Y) {
    extern __shared__ uint32_t su[];
    uint32_t* Qs = su;
    uint32_t* Ks = su + OFF_K;
    uint32_t* Vs = su + OFF_V;
    uint32_t* Ps = su + OFF_P;

    const int bx = blockIdx.x, h = blockIdx.y, b = blockIdx.z;
    const int g = h >> 3;                   // N_REP = 8
    const int tid = threadIdx.x, warp = tid >> 5, lane = tid & 31;
    const int gid = lane >> 2, tig = lane & 3;
    const int q0 = bx * BQ;
    const int w16 = warp * 16;
    const float scale = 0.08838834764831845f;   // 1/sqrt(128)

    // Load + scale + cvt Q tile (128 x 128)
#pragma unroll
    for (int i = 0; i < 16; i++) {
        int idx = i * 256 + tid;
        int row = idx >> 5;
        int c   = (idx & 31) << 2;
        float4 qv = *(const float4*)(Q + ((size_t)((b * T_ + q0 + row) * NH + h)) * HD_ + c);
        uint32_t* dst = &Qs[row * QSTR + c];
        dst[0] = f2tf32(qv.x * scale); dst[1] = f2tf32(qv.y * scale);
        dst[2] = f2tf32(qv.z * scale); dst[3] = f2tf32(qv.w * scale);
    }

    float m0 = -INFINITY, m1 = -INFINITY, l0 = 0.0f, l1 = 0.0f;
    float O[16][4];
#pragma unroll
    for (int ni = 0; ni < 16; ni++)
        O[ni][0] = O[ni][1] = O[ni][2] = O[ni][3] = 0.0f;

    const int nkv = 2 * bx + 2;
    for (int kt = 0; kt < nkv; kt++) {
        __syncthreads();    // protect Ks/Vs reuse (and Q load on first iter)
#pragma unroll
        for (int i = 0; i < 8; i++) {
            int idx = i * 256 + tid;
            int row = idx >> 5;
            int c   = (idx & 31) << 2;
            size_t base = ((size_t)((b * T_ + kt * BKV + row) * NKV + g)) * HD_ + c;
            float4 kv4 = *(const float4*)(K + base);
            float4 vv4 = *(const float4*)(V + base);
            uint32_t* dk = &Ks[row * KSTR + c];
            dk[0] = f2tf32(kv4.x); dk[1] = f2tf32(kv4.y);
            dk[2] = f2tf32(kv4.z); dk[3] = f2tf32(kv4.w);
            uint32_t* dv = &Vs[row * VSTR + c];
            dv[0] = f2tf32(vv4.x); dv[1] = f2tf32(vv4.y);
            dv[2] = f2tf32(vv4.z); dv[3] = f2tf32(vv4.w);
        }
        __syncthreads();

        // --- scores S[16 x 64] per warp ---
        float s[8][4] = {};
#pragma unroll
        for (int kk = 0; kk < 16; kk++) {
            int ar = (w16 + gid) * QSTR + kk * 8 + tig;
            uint32_t a0 = Qs[ar], a1 = Qs[ar + 8 * QSTR];
            uint32_t a2 = Qs[ar + 4], a3 = Qs[ar + 8 * QSTR + 4];
#pragma unroll
            for (int ni = 0; ni < 8; ni++) {
                int br = (ni * 8 + gid) * KSTR + kk * 8 + tig;
                mma_tf32(s[ni], a0, a1, a2, a3, Ks[br], Ks[br + 4]);
            }
        }

        // causal mask (only last two kv tiles can cross the diagonal)
        if (kt >= 2 * bx) {
            int s0 = kt * BKV;
            int r_lo = q0 + w16 + gid, r_hi = r_lo + 8;
#pragma unroll
            for (int ni = 0; ni < 8; ni++) {
                int col = s0 + ni * 8 + 2 * tig;
                if (col     > r_lo) s[ni][0] = -INFINITY;
                if (col + 1 > r_lo) s[ni][1] = -INFINITY;
                if (col     > r_hi) s[ni][2] = -INFINITY;
                if (col + 1 > r_hi) s[ni][3] = -INFINITY;
            }
        }

        // --- online softmax (rows gid and gid+8 of this warp) ---
        float mx0 = -INFINITY, mx1 = -INFINITY;
#pragma unroll
        for (int ni = 0; ni < 8; ni++) {
            mx0 = fmaxf(mx0, fmaxf(s[ni][0], s[ni][1]));
            mx1 = fmaxf(mx1, fmaxf(s[ni][2], s[ni][3]));
        }
        mx0 = fmaxf(mx0, __shfl_xor_sync(0xffffffffu, mx0, 1));
        mx0 = fmaxf(mx0, __shfl_xor_sync(0xffffffffu, mx0, 2));
        mx1 = fmaxf(mx1, __shfl_xor_sync(0xffffffffu, mx1, 1));
        mx1 = fmaxf(mx1, __shfl_xor_sync(0xffffffffu, mx1, 2));

        float mn0 = fmaxf(m0, mx0), mn1 = fmaxf(m1, mx1);
        float al0 = __expf(m0 - mn0), al1 = __expf(m1 - mn1);
        m0 = mn0; m1 = mn1;

        float ps0 = 0.0f, ps1 = 0.0f;
#pragma unroll
        for (int ni = 0; ni < 8; ni++) {
            float p0 = __expf(s[ni][0] - mn0);
            float p1 = __expf(s[ni][1] - mn0);
            float p2 = __expf(s[ni][2] - mn1);
            float p3 = __expf(s[ni][3] - mn1);
            ps0 += p0 + p1;
            ps1 += p2 + p3;
            int pr = (w16 + gid) * PSTR + ni * 8 + 2 * tig;
            Ps[pr]     = f2tf32(p0);
            Ps[pr + 1] = f2tf32(p1);
            Ps[pr + 8 * PSTR]     = f2tf32(p2);
            Ps[pr + 8 * PSTR + 1] = f2tf32(p3);
        }
        ps0 += __shfl_xor_sync(0xffffffffu, ps0, 1);
        ps0 += __shfl_xor_sync(0xffffffffu, ps0, 2);
        ps1 += __shfl_xor_sync(0xffffffffu, ps1, 1);
        ps1 += __shfl_xor_sync(0xffffffffu, ps1, 2);
        l0 = l0 * al0 + ps0;
        l1 = l1 * al1 + ps1;

#pragma unroll
        for (int ni = 0; ni < 16; ni++) {
            O[ni][0] *= al0; O[ni][1] *= al0;
            O[ni][2] *= al1; O[ni][3] *= al1;
        }
        __syncwarp();   // Ps written and read by the same warp

        // --- PV: O[16 x 128] += P[16 x 64] * V[64 x 128] ---
#pragma unroll
        for (int kk = 0; kk < 8; kk++) {
            int ar = (w16 + gid) * PSTR + kk * 8 + tig;
            uint32_t a0 = Ps[ar], a1 = Ps[ar + 8 * PSTR];
            uint32_t a2 = Ps[ar + 4], a3 = Ps[ar + 8 * PSTR + 4];
#pragma unroll
            for (int ni = 0; ni < 16; ni++) {
                int br = (kk * 8 + tig) * VSTR + ni * 8 + gid;
                mma_tf32(O[ni], a0, a1, a2, a3, Vs[br], Vs[br + 4 * VSTR]);
            }
        }
        __syncwarp();   // Ps reads done before next tile overwrites
    }

    // Epilogue
    float inv0 = 1.0f / l0, inv1 = 1.0f / l1;
    int row0 = q0 + w16 + gid, row1 = row0 + 8;
#pragma unroll
    for (int ni = 0; ni < 16; ni++) {
        int col = ni * 8 + 2 * tig;
        float2 lo = {O[ni][0] * inv0, O[ni][1] * inv0};
        float2 hi = {O[ni][2] * inv1, O[ni][3] * inv1};
        *(float2*)(Y + ((size_t)((b * T_ + row0) * NH + h)) * HD_ + col) = lo;
        *(float2*)(Y + ((size_t)((b * T_ + row1) * NH + h)) * HD_ + col) = hi;
    }
}

// ---------------------------------------------------------------------------
// Launch
// ---------------------------------------------------------------------------
extern "C" void kernel_launch(void* const* d_in, const int* in_sizes, int n_in,
                              void* d_out, int out_size) {
    const float* x    = (const float*)d_in[0];
    const float* cosp = (const float*)d_in[1];
    const float* sinp = (const float*)d_in[2];
    const float* Wq   = (const float*)d_in[3];
    const float* Wk   = (const float*)d_in[4];
    const float* Wv   = (const float*)d_in[5];
    const float* Wo   = (const float*)d_in[6];
    float* out = (float*)d_out;

    float *q, *k, *v, *y;
    cudaGetSymbolAddress((void**)&q, g_q);
    cudaGetSymbolAddress((void**)&k, g_k);
    cudaGetSymbolAddress((void**)&v, g_v);
    cudaGetSymbolAddress((void**)&y, g_y);

    cudaFuncSetAttribute(flash_tf32, cudaFuncAttributeMaxDynamicSharedMemorySize,
                         FLASH_SMEM_BYTES);

    dim3 blk(256);
    // QKV projections (TF32 tensor cores)
    tf32_gemm_nt<<<dim3(HID_ / 128, MROWS / 128), blk>>>(x, Wq, q, MROWS, HID_, HID_);
    tf32_gemm_nt<<<dim3((NKV * HD_) / 128, MROWS / 128), blk>>>(x, Wk, k, MROWS, NKV * HD_, HID_);
    tf32_gemm_nt<<<dim3((NKV * HD_) / 128, MROWS / 128), blk>>>(x, Wv, v, MROWS, NKV * HD_, HID_);
    // RoPE + RMSNorm on Q and K
    rope_rms<<<(MROWS * (NH + NKV)) / 8, blk>>>(q, k, cosp, sinp);
    // Causal GQA flash attention (TF32 tensor cores)
    flash_tf32<<<dim3(T_ / BQ, NH, B_), blk, FLASH_SMEM_BYTES>>>(q, k, v, y);
    // Output projection (TF32 tensor cores)
    tf32_gemm_nt<<<dim3(HID_ / 128, MROWS / 128), blk>>>(y, Wo, out, MROWS, HID_, HID_);
}

// round 4
// speedup vs baseline: 5.9585x; 1.6533x over previous
#include <cuda_runtime.h>
#include <cuda_fp16.h>
#include <math.h>
#include <stdint.h>

// Problem constants
#define B_    4
#define T_    2048
#define HID_  2048
#define NH    16
#define NKV   2
#define HD_   128
#define MROWS (B_ * T_)   // 8192

// Scratch (allocation-free rule: __device__ globals)
__device__ float g_q[(size_t)MROWS * HID_];
__device__ float g_k[(size_t)MROWS * NKV * HD_];
__device__ float g_v[(size_t)MROWS * NKV * HD_];
__device__ float g_y[(size_t)MROWS * HID_];

__device__ __forceinline__ uint32_t packh2(float lo, float hi) {
    __half2 h = __floats2half2_rn(lo, hi);
    return *(uint32_t*)&h;
}

__device__ __forceinline__ void mma_f16(float c[4],
                                        uint32_t a0, uint32_t a1, uint32_t a2, uint32_t a3,
                                        uint32_t b0, uint32_t b1) {
    asm volatile(
        "mma.sync.aligned.m16n8k16.row.col.f32.f16.f16.f32 "
        "{%0,%1,%2,%3}, {%4,%5,%6,%7}, {%8,%9}, {%0,%1,%2,%3};"
        : "+f"(c[0]), "+f"(c[1]), "+f"(c[2]), "+f"(c[3])
        : "r"(a0), "r"(a1), "r"(a2), "r"(a3), "r"(b0), "r"(b1));
}

#define LDMX4(r0, r1, r2, r3, addr)                                             \
    asm volatile("ldmatrix.sync.aligned.m8n8.x4.shared.b16 {%0,%1,%2,%3}, [%4];" \
                 : "=r"(r0), "=r"(r1), "=r"(r2), "=r"(r3) : "r"(addr))

#define LDMX4T(r0, r1, r2, r3, addr)                                                  \
    asm volatile("ldmatrix.sync.aligned.m8n8.x4.trans.shared.b16 {%0,%1,%2,%3}, [%4];" \
                 : "=r"(r0), "=r"(r1), "=r"(r2), "=r"(r3) : "r"(addr))

// ---------------------------------------------------------------------------
// FP16 tensor-core GEMM (NT): C[M,N] = A[M,K] * B[N,K]^T, row-major fp32 I/O.
// 128x128x32 block tile, 256 threads = 8 warps, warp tile 64x32,
// mma.m16n8k16.f16 with fp32 accumulate. Inputs cvt.rn to fp16 at smem store.
// smem: half2 words, row stride 20 words (16 data + 4 pad); 20 % 32 drives
// conflict-free ldmatrix phases (banks 20*r mod 32 distinct for r=0..7).
// ---------------------------------------------------------------------------
#define SA2 20

__global__ __launch_bounds__(256) void f16_gemm_nt(const float* __restrict__ A,
                                                   const float* __restrict__ Bm,
                                                   float* __restrict__ C,
                                                   int M, int N, int K) {
    __shared__ __align__(16) uint32_t As[128 * SA2];
    __shared__ __align__(16) uint32_t Bs[128 * SA2];

    const int tid  = threadIdx.x;
    const int lane = tid & 31, warp = tid >> 5;
    const int gid  = lane >> 2, tig = lane & 3;
    const int wm   = (warp >> 2) * 64;
    const int wn   = (warp & 3) * 32;
    const int bm   = blockIdx.y * 128;
    const int bn   = blockIdx.x * 128;

    const uint32_t as_base = (uint32_t)__cvta_generic_to_shared(As);
    const uint32_t bs_base = (uint32_t)__cvta_generic_to_shared(Bs);

    // ldmatrix lane-role offsets
    const int a_row = (lane & 7) + ((lane >> 3) & 1) * 8;   // + mi*16 + wm
    const int a_cw  = (lane >> 4) * 4;                      // + kk*8
    const int b_row = (lane & 7) + (lane >> 4) * 8;         // + nb*16 + wn
    const int b_cw  = ((lane >> 3) & 1) * 4;                // + kk*8

    float acc[4][4][4] = {};

    float4 pa[4], pb[4];
#pragma unroll
    for (int i = 0; i < 4; i++) {
        int idx = i * 256 + tid;
        int row = idx >> 3, kc = (idx & 7) << 2;
        pa[i] = *(const float4*)(A  + (size_t)(bm + row) * K + kc);
        pb[i] = *(const float4*)(Bm + (size_t)(bn + row) * K + kc);
    }

    for (int k0 = 0; k0 < K; k0 += 32) {
        __syncthreads();
#pragma unroll
        for (int i = 0; i < 4; i++) {
            int idx = i * 256 + tid;
            int row = idx >> 3, w = (idx & 7) << 1;
            uint2 ua = {packh2(pa[i].x, pa[i].y), packh2(pa[i].z, pa[i].w)};
            uint2 ub = {packh2(pb[i].x, pb[i].y), packh2(pb[i].z, pb[i].w)};
            *(uint2*)&As[row * SA2 + w] = ua;
            *(uint2*)&Bs[row * SA2 + w] = ub;
        }
        __syncthreads();

        if (k0 + 32 < K) {
#pragma unroll
            for (int i = 0; i < 4; i++) {
                int idx = i * 256 + tid;
                int row = idx >> 3, kc = (idx & 7) << 2;
                pa[i] = *(const float4*)(A  + (size_t)(bm + row) * K + k0 + 32 + kc);
                pb[i] = *(const float4*)(Bm + (size_t)(bn + row) * K + k0 + 32 + kc);
            }
        }

#pragma unroll
        for (int kk = 0; kk < 2; kk++) {          // two k16 chunks
            uint32_t af[4][4], bf[4][2];
#pragma unroll
            for (int mi = 0; mi < 4; mi++) {
                uint32_t addr = as_base +
                    (((wm + mi * 16 + a_row) * SA2 + kk * 8 + a_cw) << 2);
                LDMX4(af[mi][0], af[mi][1], af[mi][2], af[mi][3], addr);
            }
#pragma unroll
            for (int nb = 0; nb < 2; nb++) {      // covers n-blocks 2nb, 2nb+1
                uint32_t addr = bs_base +
                    (((wn + nb * 16 + b_row) * SA2 + kk * 8 + b_cw) << 2);
                LDMX4(bf[2 * nb][0], bf[2 * nb][1], bf[2 * nb + 1][0], bf[2 * nb + 1][1], addr);
            }
#pragma unroll
            for (int mi = 0; mi < 4; mi++)
#pragma unroll
                for (int ni = 0; ni < 4; ni++)
                    mma_f16(acc[mi][ni], af[mi][0], af[mi][1], af[mi][2], af[mi][3],
                            bf[ni][0], bf[ni][1]);
        }
    }

#pragma unroll
    for (int mi = 0; mi < 4; mi++)
#pragma unroll
        for (int ni = 0; ni < 4; ni++) {
            int row = bm + wm + mi * 16 + gid;
            int col = bn + wn + ni * 8 + 2 * tig;
            float2 lo = {acc[mi][ni][0], acc[mi][ni][1]};
            float2 hi = {acc[mi][ni][2], acc[mi][ni][3]};
            *(float2*)(C + (size_t)row * N + col)       = lo;
            *(float2*)(C + (size_t)(row + 8) * N + col) = hi;
        }
}

// ---------------------------------------------------------------------------
// Fused RoPE + RMSNorm (fp32, unchanged).
// ---------------------------------------------------------------------------
__global__ __launch_bounds__(256) void rope_rms(float* __restrict__ q,
                                                float* __restrict__ k,
                                                const float* __restrict__ cosp,
                                                const float* __restrict__ sinp) {
    int gw   = (blockIdx.x * 256 + threadIdx.x) >> 5;
    int lane = threadIdx.x & 31;
    const int QROWS = MROWS * NH;
    const int KROWS = MROWS * NKV;

    float* ptr;
    int t;
    if (gw < QROWS) {
        t = (gw >> 4) & (T_ - 1);
        ptr = q + (size_t)gw * HD_;
    } else {
        int r = gw - QROWS;
        if (r >= KROWS) return;
        t = (r >> 1) & (T_ - 1);
        ptr = k + (size_t)r * HD_;
    }

    float2 x0 = *(const float2*)(ptr + 2 * lane);
    float2 x1 = *(const float2*)(ptr + 2 * (lane + 32));
    float c0  = cosp[t * 64 + lane],      sn0 = sinp[t * 64 + lane];
    float c1  = cosp[t * 64 + lane + 32], sn1 = sinp[t * 64 + lane + 32];

    float o0r = x0.x * c0 - x0.y * sn0;
    float o0i = x0.x * sn0 + x0.y * c0;
    float o1r = x1.x * c1 - x1.y * sn1;
    float o1i = x1.x * sn1 + x1.y * c1;

    float ss = o0r * o0r + o0i * o0i + o1r * o1r + o1i * o1i;
#pragma unroll
    for (int off = 16; off > 0; off >>= 1)
        ss += __shfl_xor_sync(0xffffffffu, ss, off);
    float sc = rsqrtf(ss * (1.0f / 128.0f) + 1.1920929e-7f);

    float2 y0 = {o0r * sc, o0i * sc};
    float2 y1 = {o1r * sc, o1i * sc};
    *(float2*)(ptr + 2 * lane)        = y0;
    *(float2*)(ptr + 2 * (lane + 32)) = y1;
}

// ---------------------------------------------------------------------------
// FP16 tensor-core flash attention (causal, GQA 8:1).
// 128 q-rows x 64 kv per block, HD=128, 256 threads = 8 warps.
// Warp w owns q rows w*16..+15. QK^T: ldmatrix A(Q) + B(K, non-trans).
// Softmax fp32 in registers. P packed straight from S C-frags into PV A-frags
// (no smem round trip). PV: V via ldmatrix.x4.trans.
// smem half layout, word stride 68 (136 halves): 68 % 32 = 4 -> conflict-free
// ldmatrix phases (banks 4*r distinct for 8 consecutive rows).
// ---------------------------------------------------------------------------
#define FH   68                               // row stride in 4B words
#define OFF_K (128 * FH)                      // 8704
#define OFF_V (OFF_K + 64 * FH)               // 13056
#define FLASH_SMEM_BYTES ((OFF_V + 64 * FH) * 4)   // 69632

__global__ __launch_bounds__(256) void flash_f16(const float* __restrict__ Q,
                                                 const float* __restrict__ K,
                                                 const float* __restrict__ V,
                                                 float* __restrict__ Y) {
    extern __shared__ uint32_t su[];
    uint32_t* Qs = su;
    uint32_t* Ks = su + OFF_K;
    uint32_t* Vs = su + OFF_V;

    const int bx = blockIdx.x, h = blockIdx.y, b = blockIdx.z;
    const int g = h >> 3;
    const int tid = threadIdx.x, warp = tid >> 5, lane = tid & 31;
    const int gid = lane >> 2, tig = lane & 3;
    const int q0 = bx * 128;
    const int w16 = warp * 16;
    const float scale = 0.08838834764831845f;

    const uint32_t qs_b = (uint32_t)__cvta_generic_to_shared(Qs);
    const uint32_t ks_b = (uint32_t)__cvta_generic_to_shared(Ks);
    const uint32_t vs_b = (uint32_t)__cvta_generic_to_shared(Vs);

    // ldmatrix lane-role offsets
    const int a_row = (lane & 7) + ((lane >> 3) & 1) * 8;  // A (Q): + w16
    const int a_cw  = (lane >> 4) * 4;                     // + kk*8
    const int kb_row = (lane & 7) + (lane >> 4) * 8;       // B (K): + nb*16
    const int kb_cw  = ((lane >> 3) & 1) * 4;              // + kk*8
    const int vb_row = (lane & 7) + ((lane >> 3) & 1) * 8; // B (V,trans): + j*16
    const int vb_cw  = (lane >> 4) * 4;                    // + nb*8

    // Load + scale + cvt Q tile (128 x 128)
#pragma unroll
    for (int i = 0; i < 16; i++) {
        int idx = i * 256 + tid;
        int row = idx >> 5;
        int c   = (idx & 31) << 2;
        float4 qv = *(const float4*)(Q + ((size_t)((b * T_ + q0 + row) * NH + h)) * HD_ + c);
        uint2 u = {packh2(qv.x * scale, qv.y * scale), packh2(qv.z * scale, qv.w * scale)};
        *(uint2*)&Qs[row * FH + (idx & 31) * 2] = u;
    }

    float m0 = -INFINITY, m1 = -INFINITY, l0 = 0.0f, l1 = 0.0f;
    float O[16][4];
#pragma unroll
    for (int ni = 0; ni < 16; ni++)
        O[ni][0] = O[ni][1] = O[ni][2] = O[ni][3] = 0.0f;

    const int nkv = 2 * bx + 2;
    for (int kt = 0; kt < nkv; kt++) {
        __syncthreads();
#pragma unroll
        for (int i = 0; i < 8; i++) {
            int idx = i * 256 + tid;
            int row = idx >> 5;
            int c   = (idx & 31) << 2;
            size_t base = ((size_t)((b * T_ + kt * 64 + row) * NKV + g)) * HD_ + c;
            float4 kv4 = *(const float4*)(K + base);
            float4 vv4 = *(const float4*)(V + base);
            uint2 uk = {packh2(kv4.x, kv4.y), packh2(kv4.z, kv4.w)};
            uint2 uv = {packh2(vv4.x, vv4.y), packh2(vv4.z, vv4.w)};
            *(uint2*)&Ks[row * FH + (idx & 31) * 2] = uk;
            *(uint2*)&Vs[row * FH + (idx & 31) * 2] = uv;
        }
        __syncthreads();

        // --- scores S[16 x 64] per warp ---
        float s[8][4] = {};
#pragma unroll
        for (int kk = 0; kk < 8; kk++) {
            uint32_t a0, a1, a2, a3;
            LDMX4(a0, a1, a2, a3,
                  qs_b + (((w16 + a_row) * FH + kk * 8 + a_cw) << 2));
#pragma unroll
            for (int nb = 0; nb < 4; nb++) {   // n-blocks 2nb, 2nb+1
                uint32_t b0, b1, b2, b3;
                LDMX4(b0, b1, b2, b3,
                      ks_b + (((nb * 16 + kb_row) * FH + kk * 8 + kb_cw) << 2));
                mma_f16(s[2 * nb],     a0, a1, a2, a3, b0, b1);
                mma_f16(s[2 * nb + 1], a0, a1, a2, a3, b2, b3);
            }
        }

        // causal mask (only last two kv tiles can cross the diagonal)
        if (kt >= 2 * bx) {
            int s0 = kt * 64;
            int r_lo = q0 + w16 + gid, r_hi = r_lo + 8;
#pragma unroll
            for (int ni = 0; ni < 8; ni++) {
                int col = s0 + ni * 8 + 2 * tig;
                if (col     > r_lo) s[ni][0] = -INFINITY;
                if (col + 1 > r_lo) s[ni][1] = -INFINITY;
                if (col     > r_hi) s[ni][2] = -INFINITY;
                if (col + 1 > r_hi) s[ni][3] = -INFINITY;
            }
        }

        // --- online softmax (rows gid and gid+8) ---
        float mx0 = -INFINITY, mx1 = -INFINITY;
#pragma unroll
        for (int ni = 0; ni < 8; ni++) {
            mx0 = fmaxf(mx0, fmaxf(s[ni][0], s[ni][1]));
            mx1 = fmaxf(mx1, fmaxf(s[ni][2], s[ni][3]));
        }
        mx0 = fmaxf(mx0, __shfl_xor_sync(0xffffffffu, mx0, 1));
        mx0 = fmaxf(mx0, __shfl_xor_sync(0xffffffffu, mx0, 2));
        mx1 = fmaxf(mx1, __shfl_xor_sync(0xffffffffu, mx1, 1));
        mx1 = fmaxf(mx1, __shfl_xor_sync(0xffffffffu, mx1, 2));

        float mn0 = fmaxf(m0, mx0), mn1 = fmaxf(m1, mx1);
        float al0 = __expf(m0 - mn0), al1 = __expf(m1 - mn1);
        m0 = mn0; m1 = mn1;

        float ps0 = 0.0f, ps1 = 0.0f;
#pragma unroll
        for (int ni = 0; ni < 8; ni++) {
            s[ni][0] = __expf(s[ni][0] - mn0);
            s[ni][1] = __expf(s[ni][1] - mn0);
            s[ni][2] = __expf(s[ni][2] - mn1);
            s[ni][3] = __expf(s[ni][3] - mn1);
            ps0 += s[ni][0] + s[ni][1];
            ps1 += s[ni][2] + s[ni][3];
        }
        ps0 += __shfl_xor_sync(0xffffffffu, ps0, 1);
        ps0 += __shfl_xor_sync(0xffffffffu, ps0, 2);
        ps1 += __shfl_xor_sync(0xffffffffu, ps1, 1);
        ps1 += __shfl_xor_sync(0xffffffffu, ps1, 2);
        l0 = l0 * al0 + ps0;
        l1 = l1 * al1 + ps1;

#pragma unroll
        for (int ni = 0; ni < 16; ni++) {
            O[ni][0] *= al0; O[ni][1] *= al0;
            O[ni][2] *= al1; O[ni][3] *= al1;
        }

        // --- PV: O[16 x 128] += P[16 x 64] * V[64 x 128]; P from registers ---
#pragma unroll
        for (int j = 0; j < 4; j++) {          // k16 chunks along kv
            uint32_t a0 = packh2(s[2 * j][0],     s[2 * j][1]);
            uint32_t a1 = packh2(s[2 * j][2],     s[2 * j][3]);
            uint32_t a2 = packh2(s[2 * j + 1][0], s[2 * j + 1][1]);
            uint32_t a3 = packh2(s[2 * j + 1][2], s[2 * j + 1][3]);
#pragma unroll
            for (int nb = 0; nb < 8; nb++) {   // O n-blocks 2nb, 2nb+1
                uint32_t b0, b1, b2, b3;
                LDMX4T(b0, b1, b2, b3,
                       vs_b + (((j * 16 + vb_row) * FH + nb * 8 + vb_cw) << 2));
                mma_f16(O[2 * nb],     a0, a1, a2, a3, b0, b1);
                mma_f16(O[2 * nb + 1], a0, a1, a2, a3, b2, b3);
            }
        }
    }

    // Epilogue
    float inv0 = 1.0f / l0, inv1 = 1.0f / l1;
    int row0 = q0 + w16 + gid, row1 = row0 + 8;
#pragma unroll
    for (int ni = 0; ni < 16; ni++) {
        int col = ni * 8 + 2 * tig;
        float2 lo = {O[ni][0] * inv0, O[ni][1] * inv0};
        float2 hi = {O[ni][2] * inv1, O[ni][3] * inv1};
        *(float2*)(Y + ((size_t)((b * T_ + row0) * NH + h)) * HD_ + col) = lo;
        *(float2*)(Y + ((size_t)((b * T_ + row1) * NH + h)) * HD_ + col) = hi;
    }
}

// ---------------------------------------------------------------------------
// Launch
// ---------------------------------------------------------------------------
extern "C" void kernel_launch(void* const* d_in, const int* in_sizes, int n_in,
                              void* d_out, int out_size) {
    const float* x    = (const float*)d_in[0];
    const float* cosp = (const float*)d_in[1];
    const float* sinp = (const float*)d_in[2];
    const float* Wq   = (const float*)d_in[3];
    const float* Wk   = (const float*)d_in[4];
    const float* Wv   = (const float*)d_in[5];
    const float* Wo   = (const float*)d_in[6];
    float* out = (float*)d_out;

    float *q, *k, *v, *y;
    cudaGetSymbolAddress((void**)&q, g_q);
    cudaGetSymbolAddress((void**)&k, g_k);
    cudaGetSymbolAddress((void**)&v, g_v);
    cudaGetSymbolAddress((void**)&y, g_y);

    cudaFuncSetAttribute(flash_f16, cudaFuncAttributeMaxDynamicSharedMemorySize,
                         FLASH_SMEM_BYTES);

    dim3 blk(256);
    // QKV projections (fp16 tensor cores, fp32 accumulate)
    f16_gemm_nt<<<dim3(HID_ / 128, MROWS / 128), blk>>>(x, Wq, q, MROWS, HID_, HID_);
    f16_gemm_nt<<<dim3((NKV * HD_) / 128, MROWS / 128), blk>>>(x, Wk, k, MROWS, NKV * HD_, HID_);
    f16_gemm_nt<<<dim3((NKV * HD_) / 128, MROWS / 128), blk>>>(x, Wv, v, MROWS, NKV * HD_, HID_);
    // RoPE + RMSNorm on Q and K
    rope_rms<<<(MROWS * (NH + NKV)) / 8, blk>>>(q, k, cosp, sinp);
    // Causal GQA flash attention (fp16 tensor cores)
    flash_f16<<<dim3(T_ / 128, NH, B_), blk, FLASH_SMEM_BYTES>>>(q, k, v, y);
    // Output projection
    f16_gemm_nt<<<dim3(HID_ / 128, MROWS / 128), blk>>>(y, Wo, out, MROWS, HID_, HID_);
}

// round 8
// speedup vs baseline: 7.8225x; 1.3128x over previous
#include <cuda_runtime.h>
#include <cuda_fp16.h>
#include <math.h>
#include <stdint.h>

// Problem constants
#define B_    4
#define T_    2048
#define HID_  2048
#define NH    16
#define NKV   2
#define HD_   128
#define MROWS (B_ * T_)   // 8192

// fp16 scratch (allocation-free rule: __device__ globals)
__device__ __half g_xh [(size_t)MROWS * HID_];
__device__ __half g_wqh[(size_t)HID_ * HID_];
__device__ __half g_wkh[(size_t)NKV * HD_ * HID_];
__device__ __half g_wvh[(size_t)NKV * HD_ * HID_];
__device__ __half g_woh[(size_t)HID_ * HID_];
__device__ __half g_qh [(size_t)MROWS * HID_];
__device__ __half g_kh [(size_t)MROWS * NKV * HD_];
__device__ __half g_vh [(size_t)MROWS * NKV * HD_];
__device__ __half g_yh [(size_t)MROWS * HID_];

// ---------------------------------------------------------------------------
// Helpers
// ---------------------------------------------------------------------------
__device__ __forceinline__ uint32_t packh2(float lo, float hi) {
    __half2 h = __floats2half2_rn(lo, hi);
    return *(uint32_t*)&h;
}

__device__ __forceinline__ void mma_f16(float c[4],
                                        uint32_t a0, uint32_t a1, uint32_t a2, uint32_t a3,
                                        uint32_t b0, uint32_t b1) {
    asm volatile(
        "mma.sync.aligned.m16n8k16.row.col.f32.f16.f16.f32 "
        "{%0,%1,%2,%3}, {%4,%5,%6,%7}, {%8,%9}, {%0,%1,%2,%3};"
        : "+f"(c[0]), "+f"(c[1]), "+f"(c[2]), "+f"(c[3])
        : "r"(a0), "r"(a1), "r"(a2), "r"(a3), "r"(b0), "r"(b1));
}

#define LDMX4(r0, r1, r2, r3, addr)                                             \
    asm volatile("ldmatrix.sync.aligned.m8n8.x4.shared.b16 {%0,%1,%2,%3}, [%4];" \
                 : "=r"(r0), "=r"(r1), "=r"(r2), "=r"(r3) : "r"(addr))

#define LDMX4T(r0, r1, r2, r3, addr)                                                  \
    asm volatile("ldmatrix.sync.aligned.m8n8.x4.trans.shared.b16 {%0,%1,%2,%3}, [%4];" \
                 : "=r"(r0), "=r"(r1), "=r"(r2), "=r"(r3) : "r"(addr))

#define CPA16(dst, src) \
    asm volatile("cp.async.cg.shared.global [%0], [%1], 16;" :: "r"(dst), "l"(src))
#define CP_COMMIT() asm volatile("cp.async.commit_group;" ::: "memory")
#define CP_WAIT(n)  asm volatile("cp.async.wait_group %0;" :: "n"(n) : "memory")

// ---------------------------------------------------------------------------
// fp32 -> fp16 convert (vectorized)
// ---------------------------------------------------------------------------
__global__ __launch_bounds__(256) void cvt16(const float* __restrict__ in,
                                             __half* __restrict__ out, int n4) {
    int i = blockIdx.x * 256 + threadIdx.x;
    if (i >= n4) return;
    float4 v = ((const float4*)in)[i];
    uint2 o = {packh2(v.x, v.y), packh2(v.z, v.w)};
    ((uint2*)out)[i] = o;
}

// ---------------------------------------------------------------------------
// FP16 GEMM (NT) with 3-stage cp.async pipeline.
// C[M,N] = A[M,K] * B[N,K]^T, fp16 in, fp16 or fp32 out (fp32 accumulate).
// 128x128x64 block tile, 256 threads = 8 warps, warp tile 64x32.
// smem rows: 64 halves = 32 words + 4 pad = 36 words (144B); 36 % 32 = 4 ->
// conflict-free ldmatrix phases. One __syncthreads per K-step.
// ---------------------------------------------------------------------------
#define GST 36                       // words per smem row
#define STG_W (128 * GST)            // words per A (or B) stage = 4608
#define STAGE_BYTES (2 * STG_W * 4)  // 36864
#define GSMEM (3 * STAGE_BYTES)      // 110592

__global__ __launch_bounds__(256) void f16_gemm_pipe(const __half* __restrict__ A,
                                                     const __half* __restrict__ Bw,
                                                     void* __restrict__ Cout,
                                                     int M, int N, int K, int out_half) {
    extern __shared__ uint32_t su[];
    const uint32_t sbase = (uint32_t)__cvta_generic_to_shared(su);

    const int tid  = threadIdx.x;
    const int lane = tid & 31, warp = tid >> 5;
    const int gid  = lane >> 2, tig = lane & 3;
    const int wm   = (warp >> 2) * 64;
    const int wn   = (warp & 3) * 32;
    const int bm   = blockIdx.y * 128;
    const int bn   = blockIdx.x * 128;

    // cp.async thread roles: 4 chunks A + 4 chunks B per stage
    const int cr = tid >> 1;              // base row group
    const int cc = tid & 1;               // chunk pair
    // per-thread: rows cr, cr+... simpler mapping below in loop

    // ldmatrix lane-role offsets
    const int a_row = (lane & 7) + ((lane >> 3) & 1) * 8;
    const int a_cw  = (lane >> 4) * 4;
    const int b_row = (lane & 7) + (lane >> 4) * 8;
    const int b_cw  = ((lane >> 3) & 1) * 4;

    const int S = K >> 6;

    auto issue = [&](int s, int buf) {
        const int k0 = s << 6;
        const uint32_t abase = sbase + buf * STAGE_BYTES;
        const uint32_t bbase = abase + STG_W * 4;
#pragma unroll
        for (int i = 0; i < 4; i++) {
            int idx = i * 256 + tid;
            int r = idx >> 3, cq = idx & 7;
            CPA16(abase + (r * GST + cq * 4) * 4,
                  A + (size_t)(bm + r) * K + k0 + cq * 8);
        }
#pragma unroll
        for (int i = 0; i < 4; i++) {
            int idx = i * 256 + tid;
            int r = idx >> 3, cq = idx & 7;
            CPA16(bbase + (r * GST + cq * 4) * 4,
                  Bw + (size_t)(bn + r) * K + k0 + cq * 8);
        }
        CP_COMMIT();
    };

    float acc[4][4][4] = {};

    issue(0, 0);
    issue(1, 1);

    for (int s = 0; s < S; s++) {
        CP_WAIT(1);
        __syncthreads();
        if (s + 2 < S) issue(s + 2, (s + 2) % 3);

        const uint32_t abase = sbase + (s % 3) * STAGE_BYTES;
        const uint32_t bbase = abase + STG_W * 4;
#pragma unroll
        for (int kk = 0; kk < 4; kk++) {
            uint32_t af[4][4], bf[4][2];
#pragma unroll
            for (int mi = 0; mi < 4; mi++) {
                uint32_t addr = abase + (((wm + mi * 16 + a_row) * GST + kk * 8 + a_cw) << 2);
                LDMX4(af[mi][0], af[mi][1], af[mi][2], af[mi][3], addr);
            }
#pragma unroll
            for (int nb = 0; nb < 2; nb++) {
                uint32_t addr = bbase + (((wn + nb * 16 + b_row) * GST + kk * 8 + b_cw) << 2);
                LDMX4(bf[2 * nb][0], bf[2 * nb][1], bf[2 * nb + 1][0], bf[2 * nb + 1][1], addr);
            }
#pragma unroll
            for (int mi = 0; mi < 4; mi++)
#pragma unroll
                for (int ni = 0; ni < 4; ni++)
                    mma_f16(acc[mi][ni], af[mi][0], af[mi][1], af[mi][2], af[mi][3],
                            bf[ni][0], bf[ni][1]);
        }
    }

#pragma unroll
    for (int mi = 0; mi < 4; mi++)
#pragma unroll
        for (int ni = 0; ni < 4; ni++) {
            int row = bm + wm + mi * 16 + gid;
            int col = bn + wn + ni * 8 + 2 * tig;
            if (out_half) {
                __half* Ch = (__half*)Cout;
                *(uint32_t*)(Ch + (size_t)row * N + col) =
                    packh2(acc[mi][ni][0], acc[mi][ni][1]);
                *(uint32_t*)(Ch + (size_t)(row + 8) * N + col) =
                    packh2(acc[mi][ni][2], acc[mi][ni][3]);
            } else {
                float* Cf = (float*)Cout;
                float2 lo = {acc[mi][ni][0], acc[mi][ni][1]};
                float2 hi = {acc[mi][ni][2], acc[mi][ni][3]};
                *(float2*)(Cf + (size_t)row * N + col)       = lo;
                *(float2*)(Cf + (size_t)(row + 8) * N + col) = hi;
            }
        }
}

// ---------------------------------------------------------------------------
// Fused RoPE + RMSNorm on fp16 buffers (fp32 math). One warp per head row.
// ---------------------------------------------------------------------------
__global__ __launch_bounds__(256) void rope_rms_h(__half* __restrict__ q,
                                                  __half* __restrict__ k,
                                                  const float* __restrict__ cosp,
                                                  const float* __restrict__ sinp) {
    int gw   = (blockIdx.x * 256 + threadIdx.x) >> 5;
    int lane = threadIdx.x & 31;
    const int QROWS = MROWS * NH;
    const int KROWS = MROWS * NKV;

    __half* hp;
    int t;
    if (gw < QROWS) {
        t = (gw >> 4) & (T_ - 1);
        hp = q + (size_t)gw * HD_;
    } else {
        int r = gw - QROWS;
        if (r >= KROWS) return;
        t = (r >> 1) & (T_ - 1);
        hp = k + (size_t)r * HD_;
    }
    uint32_t* ptr = (uint32_t*)hp;

    float2 x0 = __half22float2(*(__half2*)&ptr[lane]);
    float2 x1 = __half22float2(*(__half2*)&ptr[lane + 32]);
    float c0  = cosp[t * 64 + lane],      sn0 = sinp[t * 64 + lane];
    float c1  = cosp[t * 64 + lane + 32], sn1 = sinp[t * 64 + lane + 32];

    float o0r = x0.x * c0 - x0.y * sn0;
    float o0i = x0.x * sn0 + x0.y * c0;
    float o1r = x1.x * c1 - x1.y * sn1;
    float o1i = x1.x * sn1 + x1.y * c1;

    float ss = o0r * o0r + o0i * o0i + o1r * o1r + o1i * o1i;
#pragma unroll
    for (int off = 16; off > 0; off >>= 1)
        ss += __shfl_xor_sync(0xffffffffu, ss, off);
    float sc = rsqrtf(ss * (1.0f / 128.0f) + 1.1920929e-7f);

    ptr[lane]      = packh2(o0r * sc, o0i * sc);
    ptr[lane + 32] = packh2(o1r * sc, o1i * sc);
}

// ---------------------------------------------------------------------------
// FP16 flash attention (causal, GQA 8:1), half in / half out.
// 128 q-rows x 64 kv per block, 256 threads. K/V tiles double-buffered with
// cp.async: load of tile kt+1 overlaps compute of tile kt.
// ---------------------------------------------------------------------------
#define FH    68                          // row stride in 4B words
#define OFF_K0 (128 * FH)                 // 8704
#define KVBUF  (2 * 64 * FH)              // words per (K,V) buffer pair = 8704
#define FLASH_SMEM_BYTES ((OFF_K0 + 2 * KVBUF) * 4)   // 104448

__global__ __launch_bounds__(256) void flash_h(const __half* __restrict__ Q,
                                               const __half* __restrict__ K,
                                               const __half* __restrict__ V,
                                               __half* __restrict__ Y) {
    extern __shared__ uint32_t su[];
    const uint32_t qs_b = (uint32_t)__cvta_generic_to_shared(su);

    const int bx = blockIdx.x, h = blockIdx.y, b = blockIdx.z;
    const int g = h >> 3;
    const int tid = threadIdx.x, warp = tid >> 5, lane = tid & 31;
    const int gid = lane >> 2, tig = lane & 3;
    const int q0 = bx * 128;
    const int w16 = warp * 16;
    const float scale = 0.08838834764831845f;

    const int a_row = (lane & 7) + ((lane >> 3) & 1) * 8;
    const int a_cw  = (lane >> 4) * 4;
    const int kb_row = (lane & 7) + (lane >> 4) * 8;
    const int kb_cw  = ((lane >> 3) & 1) * 4;
    const int vb_row = (lane & 7) + ((lane >> 3) & 1) * 8;
    const int vb_cw  = (lane >> 4) * 4;

    const int nkv = 2 * bx + 2;

    auto issue_kv = [&](int kt, int buf) {
        const uint32_t kbase = qs_b + (OFF_K0 + buf * KVBUF) * 4;
        const uint32_t vbase = kbase + 64 * FH * 4;
#pragma unroll
        for (int i = 0; i < 4; i++) {
            int idx = i * 256 + tid;
            int row = idx >> 4, cq = idx & 15;
            size_t base = ((size_t)((b * T_ + kt * 64 + row) * NKV + g)) * HD_ + cq * 8;
            CPA16(kbase + (row * FH + cq * 4) * 4, K + base);
            CPA16(vbase + (row * FH + cq * 4) * 4, V + base);
        }
        CP_COMMIT();
    };

    issue_kv(0, 0);

    // Q tile (raw uint4 copy)
#pragma unroll
    for (int i = 0; i < 8; i++) {
        int idx = i * 256 + tid;
        int row = idx >> 4, cq = idx & 15;
        *(uint4*)&su[row * FH + cq * 4] =
            *(const uint4*)(Q + ((size_t)((b * T_ + q0 + row) * NH + h)) * HD_ + cq * 8);
    }

    float m0 = -INFINITY, m1 = -INFINITY, l0 = 0.0f, l1 = 0.0f;
    float O[16][4];
#pragma unroll
    for (int ni = 0; ni < 16; ni++)
        O[ni][0] = O[ni][1] = O[ni][2] = O[ni][3] = 0.0f;

    for (int kt = 0; kt < nkv; kt++) {
        const int buf = kt & 1;
        CP_WAIT(0);
        __syncthreads();
        if (kt + 1 < nkv) issue_kv(kt + 1, buf ^ 1);

        const uint32_t ks_b = qs_b + (OFF_K0 + buf * KVBUF) * 4;
        const uint32_t vs_b = ks_b + 64 * FH * 4;

        float s[8][4] = {};
#pragma unroll
        for (int kk = 0; kk < 8; kk++) {
            uint32_t a0, a1, a2, a3;
            LDMX4(a0, a1, a2, a3, qs_b + (((w16 + a_row) * FH + kk * 8 + a_cw) << 2));
#pragma unroll
            for (int nb = 0; nb < 4; nb++) {
                uint32_t b0, b1, b2, b3;
                LDMX4(b0, b1, b2, b3,
                      ks_b + (((nb * 16 + kb_row) * FH + kk * 8 + kb_cw) << 2));
                mma_f16(s[2 * nb],     a0, a1, a2, a3, b0, b1);
                mma_f16(s[2 * nb + 1], a0, a1, a2, a3, b2, b3);
            }
        }
#pragma unroll
        for (int ni = 0; ni < 8; ni++) {
            s[ni][0] *= scale; s[ni][1] *= scale;
            s[ni][2] *= scale; s[ni][3] *= scale;
        }

        if (kt >= 2 * bx) {
            int s0 = kt * 64;
            int r_lo = q0 + w16 + gid, r_hi = r_lo + 8;
#pragma unroll
            for (int ni = 0; ni < 8; ni++) {
                int col = s0 + ni * 8 + 2 * tig;
                if (col     > r_lo) s[ni][0] = -INFINITY;
                if (col + 1 > r_lo) s[ni][1] = -INFINITY;
                if (col     > r_hi) s[ni][2] = -INFINITY;
                if (col + 1 > r_hi) s[ni][3] = -INFINITY;
            }
        }

        float mx0 = -INFINITY, mx1 = -INFINITY;
#pragma unroll
        for (int ni = 0; ni < 8; ni++) {
            mx0 = fmaxf(mx0, fmaxf(s[ni][0], s[ni][1]));
            mx1 = fmaxf(mx1, fmaxf(s[ni][2], s[ni][3]));
        }
        mx0 = fmaxf(mx0, __shfl_xor_sync(0xffffffffu, mx0, 1));
        mx0 = fmaxf(mx0, __shfl_xor_sync(0xffffffffu, mx0, 2));
        mx1 = fmaxf(mx1, __shfl_xor_sync(0xffffffffu, mx1, 1));
        mx1 = fmaxf(mx1, __shfl_xor_sync(0xffffffffu, mx1, 2));

        float mn0 = fmaxf(m0, mx0), mn1 = fmaxf(m1, mx1);
        float al0 = __expf(m0 - mn0), al1 = __expf(m1 - mn1);
        m0 = mn0; m1 = mn1;

        float ps0 = 0.0f, ps1 = 0.0f;
#pragma unroll
        for (int ni = 0; ni < 8; ni++) {
            s[ni][0] = __expf(s[ni][0] - mn0);
            s[ni][1] = __expf(s[ni][1] - mn0);
            s[ni][2] = __expf(s[ni][2] - mn1);
            s[ni][3] = __expf(s[ni][3] - mn1);
            ps0 += s[ni][0] + s[ni][1];
            ps1 += s[ni][2] + s[ni][3];
        }
        ps0 += __shfl_xor_sync(0xffffffffu, ps0, 1);
        ps0 += __shfl_xor_sync(0xffffffffu, ps0, 2);
        ps1 += __shfl_xor_sync(0xffffffffu, ps1, 1);
        ps1 += __shfl_xor_sync(0xffffffffu, ps1, 2);
        l0 = l0 * al0 + ps0;
        l1 = l1 * al1 + ps1;

#pragma unroll
        for (int ni = 0; ni < 16; ni++) {
            O[ni][0] *= al0; O[ni][1] *= al0;
            O[ni][2] *= al1; O[ni][3] *= al1;
        }

#pragma unroll
        for (int j = 0; j < 4; j++) {
            uint32_t a0 = packh2(s[2 * j][0],     s[2 * j][1]);
            uint32_t a1 = packh2(s[2 * j][2],     s[2 * j][3]);
            uint32_t a2 = packh2(s[2 * j + 1][0], s[2 * j + 1][1]);
            uint32_t a3 = packh2(s[2 * j + 1][2], s[2 * j + 1][3]);
#pragma unroll
            for (int nb = 0; nb < 8; nb++) {
                uint32_t b0, b1, b2, b3;
                LDMX4T(b0, b1, b2, b3,
                       vs_b + (((j * 16 + vb_row) * FH + nb * 8 + vb_cw) << 2));
                mma_f16(O[2 * nb],     a0, a1, a2, a3, b0, b1);
                mma_f16(O[2 * nb + 1], a0, a1, a2, a3, b2, b3);
            }
        }
    }

    float inv0 = 1.0f / l0, inv1 = 1.0f / l1;
    int row0 = q0 + w16 + gid, row1 = row0 + 8;
#pragma unroll
    for (int ni = 0; ni < 16; ni++) {
        int col = ni * 8 + 2 * tig;
        *(uint32_t*)(Y + ((size_t)((b * T_ + row0) * NH + h)) * HD_ + col) =
            packh2(O[ni][0] * inv0, O[ni][1] * inv0);
        *(uint32_t*)(Y + ((size_t)((b * T_ + row1) * NH + h)) * HD_ + col) =
            packh2(O[ni][2] * inv1, O[ni][3] * inv1);
    }
}

// ---------------------------------------------------------------------------
// Launch
// ---------------------------------------------------------------------------
extern "C" void kernel_launch(void* const* d_in, const int* in_sizes, int n_in,
                              void* d_out, int out_size) {
    const float* x    = (const float*)d_in[0];
    const float* cosp = (const float*)d_in[1];
    const float* sinp = (const float*)d_in[2];
    const float* Wq   = (const float*)d_in[3];
    const float* Wk   = (const float*)d_in[4];
    const float* Wv   = (const float*)d_in[5];
    const float* Wo   = (const float*)d_in[6];
    float* out = (float*)d_out;

    __half *xh, *wqh, *wkh, *wvh, *woh, *qh, *kh, *vh, *yh;
    cudaGetSymbolAddress((void**)&xh,  g_xh);
    cudaGetSymbolAddress((void**)&wqh, g_wqh);
    cudaGetSymbolAddress((void**)&wkh, g_wkh);
    cudaGetSymbolAddress((void**)&wvh, g_wvh);
    cudaGetSymbolAddress((void**)&woh, g_woh);
    cudaGetSymbolAddress((void**)&qh,  g_qh);
    cudaGetSymbolAddress((void**)&kh,  g_kh);
    cudaGetSymbolAddress((void**)&vh,  g_vh);
    cudaGetSymbolAddress((void**)&yh,  g_yh);

    cudaFuncSetAttribute(f16_gemm_pipe, cudaFuncAttributeMaxDynamicSharedMemorySize, GSMEM);
    cudaFuncSetAttribute(flash_h, cudaFuncAttributeMaxDynamicSharedMemorySize,
                         FLASH_SMEM_BYTES);

    dim3 blk(256);
    // fp32 -> fp16 converts (once)
    cvt16<<<(MROWS * HID_ / 4 + 255) / 256, blk>>>(x,  xh,  MROWS * HID_ / 4);
    cvt16<<<(HID_ * HID_ / 4 + 255) / 256, blk>>>(Wq, wqh, HID_ * HID_ / 4);
    cvt16<<<(NKV * HD_ * HID_ / 4 + 255) / 256, blk>>>(Wk, wkh, NKV * HD_ * HID_ / 4);
    cvt16<<<(NKV * HD_ * HID_ / 4 + 255) / 256, blk>>>(Wv, wvh, NKV * HD_ * HID_ / 4);
    cvt16<<<(HID_ * HID_ / 4 + 255) / 256, blk>>>(Wo, woh, HID_ * HID_ / 4);

    // Projections (fp16 mma.sync, cp.async pipelined, fp32 accumulate)
    f16_gemm_pipe<<<dim3(HID_ / 128, MROWS / 128), blk, GSMEM>>>(xh, wqh, qh, MROWS, HID_, HID_, 1);
    f16_gemm_pipe<<<dim3((NKV * HD_) / 128, MROWS / 128), blk, GSMEM>>>(xh, wkh, kh, MROWS, NKV * HD_, HID_, 1);
    f16_gemm_pipe<<<dim3((NKV * HD_) / 128, MROWS / 128), blk, GSMEM>>>(xh, wvh, vh, MROWS, NKV * HD_, HID_, 1);
    // RoPE + RMSNorm (fp16 in/out, fp32 math)
    rope_rms_h<<<(MROWS * (NH + NKV)) / 8, blk>>>(qh, kh, cosp, sinp);
    // Flash attention (fp16 mma.sync, cp.async double-buffered K/V)
    flash_h<<<dim3(T_ / 128, NH, B_), blk, FLASH_SMEM_BYTES>>>(qh, kh, vh, yh);
    // Output projection -> fp32 out
    f16_gemm_pipe<<<dim3(HID_ / 128, MROWS / 128), blk, GSMEM>>>(yh, woh, out, MROWS, HID_, HID_, 0);
}

// round 9
// speedup vs baseline: 8.0541x; 1.0296x over previous
#include <cuda_runtime.h>
#include <cuda_fp16.h>
#include <math.h>
#include <stdint.h>

// Problem constants
#define B_    4
#define T_    2048
#define HID_  2048
#define NH    16
#define NKV   2
#define HD_   128
#define MROWS (B_ * T_)   // 8192

// fp16 scratch (allocation-free rule: __device__ globals)
__device__ __half g_xh  [(size_t)MROWS * HID_];
__device__ __half g_wqh [(size_t)HID_ * HID_];
__device__ __half g_wkvh[(size_t)2 * NKV * HD_ * HID_];   // Wk rows 0-255, Wv rows 256-511
__device__ __half g_woh [(size_t)HID_ * HID_];
__device__ __half g_qh  [(size_t)MROWS * HID_];
__device__ __half g_kvh [(size_t)MROWS * 2 * NKV * HD_];  // [row, 512]: k@g*128, v@256+g*128
__device__ __half g_yh  [(size_t)MROWS * HID_];

// ---------------------------------------------------------------------------
// Helpers
// ---------------------------------------------------------------------------
__device__ __forceinline__ uint32_t packh2(float lo, float hi) {
    __half2 h = __floats2half2_rn(lo, hi);
    return *(uint32_t*)&h;
}

__device__ __forceinline__ void mma_f16(float c[4],
                                        uint32_t a0, uint32_t a1, uint32_t a2, uint32_t a3,
                                        uint32_t b0, uint32_t b1) {
    asm volatile(
        "mma.sync.aligned.m16n8k16.row.col.f32.f16.f16.f32 "
        "{%0,%1,%2,%3}, {%4,%5,%6,%7}, {%8,%9}, {%0,%1,%2,%3};"
        : "+f"(c[0]), "+f"(c[1]), "+f"(c[2]), "+f"(c[3])
        : "r"(a0), "r"(a1), "r"(a2), "r"(a3), "r"(b0), "r"(b1));
}

#define LDMX4(r0, r1, r2, r3, addr)                                             \
    asm volatile("ldmatrix.sync.aligned.m8n8.x4.shared.b16 {%0,%1,%2,%3}, [%4];" \
                 : "=r"(r0), "=r"(r1), "=r"(r2), "=r"(r3) : "r"(addr))

#define LDMX4T(r0, r1, r2, r3, addr)                                                  \
    asm volatile("ldmatrix.sync.aligned.m8n8.x4.trans.shared.b16 {%0,%1,%2,%3}, [%4];" \
                 : "=r"(r0), "=r"(r1), "=r"(r2), "=r"(r3) : "r"(addr))

#define CPA16(dst, src) \
    asm volatile("cp.async.cg.shared.global [%0], [%1], 16;" :: "r"(dst), "l"(src))
#define CP_COMMIT() asm volatile("cp.async.commit_group;" ::: "memory")
#define CP_WAIT(n)  asm volatile("cp.async.wait_group %0;" :: "n"(n) : "memory")

// ---------------------------------------------------------------------------
// fp32 -> fp16 convert (vectorized)
// ---------------------------------------------------------------------------
__global__ __launch_bounds__(256) void cvt16(const float* __restrict__ in,
                                             __half* __restrict__ out, int n4) {
    int i = blockIdx.x * 256 + threadIdx.x;
    if (i >= n4) return;
    float4 v = ((const float4*)in)[i];
    uint2 o = {packh2(v.x, v.y), packh2(v.z, v.w)};
    ((uint2*)out)[i] = o;
}

// ---------------------------------------------------------------------------
// FP16 GEMM (NT) with 3-stage cp.async pipeline. (unchanged from R8)
// C[M,N] = A[M,K] * B[N,K]^T, fp16 in, fp16 or fp32 out (fp32 accumulate).
// 128x128x64 block tile, 256 threads = 8 warps, warp tile 64x32.
// ---------------------------------------------------------------------------
#define GST 36
#define STG_W (128 * GST)
#define STAGE_BYTES (2 * STG_W * 4)
#define GSMEM (3 * STAGE_BYTES)      // 110592

__global__ __launch_bounds__(256) void f16_gemm_pipe(const __half* __restrict__ A,
                                                     const __half* __restrict__ Bw,
                                                     void* __restrict__ Cout,
                                                     int M, int N, int K, int out_half) {
    extern __shared__ uint32_t su[];
    const uint32_t sbase = (uint32_t)__cvta_generic_to_shared(su);

    const int tid  = threadIdx.x;
    const int lane = tid & 31, warp = tid >> 5;
    const int gid  = lane >> 2, tig = lane & 3;
    const int wm   = (warp >> 2) * 64;
    const int wn   = (warp & 3) * 32;
    const int bm   = blockIdx.y * 128;
    const int bn   = blockIdx.x * 128;

    const int a_row = (lane & 7) + ((lane >> 3) & 1) * 8;
    const int a_cw  = (lane >> 4) * 4;
    const int b_row = (lane & 7) + (lane >> 4) * 8;
    const int b_cw  = ((lane >> 3) & 1) * 4;

    const int S = K >> 6;

    auto issue = [&](int s, int buf) {
        const int k0 = s << 6;
        const uint32_t abase = sbase + buf * STAGE_BYTES;
        const uint32_t bbase = abase + STG_W * 4;
#pragma unroll
        for (int i = 0; i < 4; i++) {
            int idx = i * 256 + tid;
            int r = idx >> 3, cq = idx & 7;
            CPA16(abase + (r * GST + cq * 4) * 4,
                  A + (size_t)(bm + r) * K + k0 + cq * 8);
        }
#pragma unroll
        for (int i = 0; i < 4; i++) {
            int idx = i * 256 + tid;
            int r = idx >> 3, cq = idx & 7;
            CPA16(bbase + (r * GST + cq * 4) * 4,
                  Bw + (size_t)(bn + r) * K + k0 + cq * 8);
        }
        CP_COMMIT();
    };

    float acc[4][4][4] = {};

    issue(0, 0);
    issue(1, 1);

    for (int s = 0; s < S; s++) {
        CP_WAIT(1);
        __syncthreads();
        if (s + 2 < S) issue(s + 2, (s + 2) % 3);

        const uint32_t abase = sbase + (s % 3) * STAGE_BYTES;
        const uint32_t bbase = abase + STG_W * 4;
#pragma unroll
        for (int kk = 0; kk < 4; kk++) {
            uint32_t af[4][4], bf[4][2];
#pragma unroll
            for (int mi = 0; mi < 4; mi++) {
                uint32_t addr = abase + (((wm + mi * 16 + a_row) * GST + kk * 8 + a_cw) << 2);
                LDMX4(af[mi][0], af[mi][1], af[mi][2], af[mi][3], addr);
            }
#pragma unroll
            for (int nb = 0; nb < 2; nb++) {
                uint32_t addr = bbase + (((wn + nb * 16 + b_row) * GST + kk * 8 + b_cw) << 2);
                LDMX4(bf[2 * nb][0], bf[2 * nb][1], bf[2 * nb + 1][0], bf[2 * nb + 1][1], addr);
            }
#pragma unroll
            for (int mi = 0; mi < 4; mi++)
#pragma unroll
                for (int ni = 0; ni < 4; ni++)
                    mma_f16(acc[mi][ni], af[mi][0], af[mi][1], af[mi][2], af[mi][3],
                            bf[ni][0], bf[ni][1]);
        }
    }

#pragma unroll
    for (int mi = 0; mi < 4; mi++)
#pragma unroll
        for (int ni = 0; ni < 4; ni++) {
            int row = bm + wm + mi * 16 + gid;
            int col = bn + wn + ni * 8 + 2 * tig;
            if (out_half) {
                __half* Ch = (__half*)Cout;
                *(uint32_t*)(Ch + (size_t)row * N + col) =
                    packh2(acc[mi][ni][0], acc[mi][ni][1]);
                *(uint32_t*)(Ch + (size_t)(row + 8) * N + col) =
                    packh2(acc[mi][ni][2], acc[mi][ni][3]);
            } else {
                float* Cf = (float*)Cout;
                float2 lo = {acc[mi][ni][0], acc[mi][ni][1]};
                float2 hi = {acc[mi][ni][2], acc[mi][ni][3]};
                *(float2*)(Cf + (size_t)row * N + col)       = lo;
                *(float2*)(Cf + (size_t)(row + 8) * N + col) = hi;
            }
        }
}

// ---------------------------------------------------------------------------
// Fused RoPE + RMSNorm on fp16 (fp32 math). One warp per 128-elem head row.
// Q rows: g_qh, row r -> r*128. K rows: g_kvh, row r -> (r>>1)*512 + (r&1)*128.
// ---------------------------------------------------------------------------
__global__ __launch_bounds__(256) void rope_rms_h(__half* __restrict__ q,
                                                  __half* __restrict__ kv,
                                                  const float* __restrict__ cosp,
                                                  const float* __restrict__ sinp) {
    int gw   = (blockIdx.x * 256 + threadIdx.x) >> 5;
    int lane = threadIdx.x & 31;
    const int QROWS = MROWS * NH;
    const int KROWS = MROWS * NKV;

    __half* hp;
    int t;
    if (gw < QROWS) {
        t = (gw >> 4) & (T_ - 1);
        hp = q + (size_t)gw * HD_;
    } else {
        int r = gw - QROWS;
        if (r >= KROWS) return;
        t = (r >> 1) & (T_ - 1);
        hp = kv + (size_t)(r >> 1) * 512 + (r & 1) * 128;
    }
    uint32_t* ptr = (uint32_t*)hp;

    float2 x0 = __half22float2(*(__half2*)&ptr[lane]);
    float2 x1 = __half22float2(*(__half2*)&ptr[lane + 32]);
    float c0  = cosp[t * 64 + lane],      sn0 = sinp[t * 64 + lane];
    float c1  = cosp[t * 64 + lane + 32], sn1 = sinp[t * 64 + lane + 32];

    float o0r = x0.x * c0 - x0.y * sn0;
    float o0i = x0.x * sn0 + x0.y * c0;
    float o1r = x1.x * c1 - x1.y * sn1;
    float o1i = x1.x * sn1 + x1.y * c1;

    float ss = o0r * o0r + o0i * o0i + o1r * o1r + o1i * o1i;
#pragma unroll
    for (int off = 16; off > 0; off >>= 1)
        ss += __shfl_xor_sync(0xffffffffu, ss, off);
    float sc = rsqrtf(ss * (1.0f / 128.0f) + 1.1920929e-7f);

    ptr[lane]      = packh2(o0r * sc, o0i * sc);
    ptr[lane + 32] = packh2(o1r * sc, o1i * sc);
}

// ---------------------------------------------------------------------------
// FP16 flash attention (causal, GQA 8:1), 128 q-rows x 128 kv per block.
// 256 threads = 8 warps; warp w owns q rows w*16..+15. KV double-buffered
// cp.async. Diagonal masking hits exactly one tile (kt == bx); nkv = bx+1.
// KV read from interleaved [row,512] buffer: k@g*128, v@256+g*128.
// ---------------------------------------------------------------------------
#define FH    68                            // row stride in 4B words
#define OFF_K0 (128 * FH)                   // Q tile words = 8704
#define KVBUF  (2 * 128 * FH)               // (K,V) words per buffer = 17408
#define FLASH_SMEM_BYTES ((OFF_K0 + 2 * KVBUF) * 4)   // 174080

__global__ __launch_bounds__(256) void flash_h(const __half* __restrict__ Q,
                                               const __half* __restrict__ KV,
                                               __half* __restrict__ Y) {
    extern __shared__ uint32_t su[];
    const uint32_t qs_b = (uint32_t)__cvta_generic_to_shared(su);

    const int bx = blockIdx.x, h = blockIdx.y, b = blockIdx.z;
    const int g = h >> 3;
    const int tid = threadIdx.x, warp = tid >> 5, lane = tid & 31;
    const int gid = lane >> 2, tig = lane & 3;
    const int q0 = bx * 128;
    const int w16 = warp * 16;
    const float scale = 0.08838834764831845f;

    const int a_row = (lane & 7) + ((lane >> 3) & 1) * 8;
    const int a_cw  = (lane >> 4) * 4;
    const int kb_row = (lane & 7) + (lane >> 4) * 8;
    const int kb_cw  = ((lane >> 3) & 1) * 4;
    const int vb_row = (lane & 7) + ((lane >> 3) & 1) * 8;
    const int vb_cw  = (lane >> 4) * 4;

    const int nkv = bx + 1;

    auto issue_kv = [&](int kt, int buf) {
        const uint32_t kbase = qs_b + (OFF_K0 + buf * KVBUF) * 4;
        const uint32_t vbase = kbase + 128 * FH * 4;
#pragma unroll
        for (int i = 0; i < 8; i++) {
            int idx = i * 256 + tid;
            int row = idx >> 4, cq = idx & 15;
            size_t base = (size_t)(b * T_ + kt * 128 + row) * 512 + g * 128 + cq * 8;
            CPA16(kbase + (row * FH + cq * 4) * 4, KV + base);
            CPA16(vbase + (row * FH + cq * 4) * 4, KV + base + 256);
        }
        CP_COMMIT();
    };

    issue_kv(0, 0);

    // Q tile (raw uint4 copy)
#pragma unroll
    for (int i = 0; i < 8; i++) {
        int idx = i * 256 + tid;
        int row = idx >> 4, cq = idx & 15;
        *(uint4*)&su[row * FH + cq * 4] =
            *(const uint4*)(Q + ((size_t)((b * T_ + q0 + row) * NH + h)) * HD_ + cq * 8);
    }

    float m0 = -INFINITY, m1 = -INFINITY, l0 = 0.0f, l1 = 0.0f;
    float O[16][4];
#pragma unroll
    for (int ni = 0; ni < 16; ni++)
        O[ni][0] = O[ni][1] = O[ni][2] = O[ni][3] = 0.0f;

    for (int kt = 0; kt < nkv; kt++) {
        const int buf = kt & 1;
        CP_WAIT(0);
        __syncthreads();
        if (kt + 1 < nkv) issue_kv(kt + 1, buf ^ 1);

        const uint32_t ks_b = qs_b + (OFF_K0 + buf * KVBUF) * 4;
        const uint32_t vs_b = ks_b + 128 * FH * 4;

        // --- scores S[16 x 128] per warp ---
        float s[16][4] = {};
#pragma unroll
        for (int kk = 0; kk < 8; kk++) {
            uint32_t a0, a1, a2, a3;
            LDMX4(a0, a1, a2, a3, qs_b + (((w16 + a_row) * FH + kk * 8 + a_cw) << 2));
#pragma unroll
            for (int nb = 0; nb < 8; nb++) {
                uint32_t b0, b1, b2, b3;
                LDMX4(b0, b1, b2, b3,
                      ks_b + (((nb * 16 + kb_row) * FH + kk * 8 + kb_cw) << 2));
                mma_f16(s[2 * nb],     a0, a1, a2, a3, b0, b1);
                mma_f16(s[2 * nb + 1], a0, a1, a2, a3, b2, b3);
            }
        }
#pragma unroll
        for (int ni = 0; ni < 16; ni++) {
            s[ni][0] *= scale; s[ni][1] *= scale;
            s[ni][2] *= scale; s[ni][3] *= scale;
        }

        if (kt == bx) {    // diagonal tile: mask col > row (within-tile coords)
            int r_lo = w16 + gid, r_hi = r_lo + 8;
#pragma unroll
            for (int ni = 0; ni < 16; ni++) {
                int col = ni * 8 + 2 * tig;
                if (col     > r_lo) s[ni][0] = -INFINITY;
                if (col + 1 > r_lo) s[ni][1] = -INFINITY;
                if (col     > r_hi) s[ni][2] = -INFINITY;
                if (col + 1 > r_hi) s[ni][3] = -INFINITY;
            }
        }

        // --- online softmax (rows gid and gid+8) ---
        float mx0 = -INFINITY, mx1 = -INFINITY;
#pragma unroll
        for (int ni = 0; ni < 16; ni++) {
            mx0 = fmaxf(mx0, fmaxf(s[ni][0], s[ni][1]));
            mx1 = fmaxf(mx1, fmaxf(s[ni][2], s[ni][3]));
        }
        mx0 = fmaxf(mx0, __shfl_xor_sync(0xffffffffu, mx0, 1));
        mx0 = fmaxf(mx0, __shfl_xor_sync(0xffffffffu, mx0, 2));
        mx1 = fmaxf(mx1, __shfl_xor_sync(0xffffffffu, mx1, 1));
        mx1 = fmaxf(mx1, __shfl_xor_sync(0xffffffffu, mx1, 2));

        float mn0 = fmaxf(m0, mx0), mn1 = fmaxf(m1, mx1);
        float al0 = __expf(m0 - mn0), al1 = __expf(m1 - mn1);
        m0 = mn0; m1 = mn1;

        float ps0 = 0.0f, ps1 = 0.0f;
#pragma unroll
        for (int ni = 0; ni < 16; ni++) {
            s[ni][0] = __expf(s[ni][0] - mn0);
            s[ni][1] = __expf(s[ni][1] - mn0);
            s[ni][2] = __expf(s[ni][2] - mn1);
            s[ni][3] = __expf(s[ni][3] - mn1);
            ps0 += s[ni][0] + s[ni][1];
            ps1 += s[ni][2] + s[ni][3];
        }
        ps0 += __shfl_xor_sync(0xffffffffu, ps0, 1);
        ps0 += __shfl_xor_sync(0xffffffffu, ps0, 2);
        ps1 += __shfl_xor_sync(0xffffffffu, ps1, 1);
        ps1 += __shfl_xor_sync(0xffffffffu, ps1, 2);
        l0 = l0 * al0 + ps0;
        l1 = l1 * al1 + ps1;

#pragma unroll
        for (int ni = 0; ni < 16; ni++) {
            O[ni][0] *= al0; O[ni][1] *= al0;
            O[ni][2] *= al1; O[ni][3] *= al1;
        }

        // --- PV: O[16 x 128] += P[16 x 128] * V[128 x 128]; P from registers ---
#pragma unroll
        for (int j = 0; j < 8; j++) {          // k16 chunks along kv
            uint32_t a0 = packh2(s[2 * j][0],     s[2 * j][1]);
            uint32_t a1 = packh2(s[2 * j][2],     s[2 * j][3]);
            uint32_t a2 = packh2(s[2 * j + 1][0], s[2 * j + 1][1]);
            uint32_t a3 = packh2(s[2 * j + 1][2], s[2 * j + 1][3]);
#pragma unroll
            for (int nb = 0; nb < 8; nb++) {
                uint32_t b0, b1, b2, b3;
                LDMX4T(b0, b1, b2, b3,
                       vs_b + (((j * 16 + vb_row) * FH + nb * 8 + vb_cw) << 2));
                mma_f16(O[2 * nb],     a0, a1, a2, a3, b0, b1);
                mma_f16(O[2 * nb + 1], a0, a1, a2, a3, b2, b3);
            }
        }
    }

    float inv0 = 1.0f / l0, inv1 = 1.0f / l1;
    int row0 = q0 + w16 + gid, row1 = row0 + 8;
#pragma unroll
    for (int ni = 0; ni < 16; ni++) {
        int col = ni * 8 + 2 * tig;
        *(uint32_t*)(Y + ((size_t)((b * T_ + row0) * NH + h)) * HD_ + col) =
            packh2(O[ni][0] * inv0, O[ni][1] * inv0);
        *(uint32_t*)(Y + ((size_t)((b * T_ + row1) * NH + h)) * HD_ + col) =
            packh2(O[ni][2] * inv1, O[ni][3] * inv1);
    }
}

// ---------------------------------------------------------------------------
// Launch
// ---------------------------------------------------------------------------
extern "C" void kernel_launch(void* const* d_in, const int* in_sizes, int n_in,
                              void* d_out, int out_size) {
    const float* x    = (const float*)d_in[0];
    const float* cosp = (const float*)d_in[1];
    const float* sinp = (const float*)d_in[2];
    const float* Wq   = (const float*)d_in[3];
    const float* Wk   = (const float*)d_in[4];
    const float* Wv   = (const float*)d_in[5];
    const float* Wo   = (const float*)d_in[6];
    float* out = (float*)d_out;

    __half *xh, *wqh, *wkvh, *woh, *qh, *kvh, *yh;
    cudaGetSymbolAddress((void**)&xh,   g_xh);
    cudaGetSymbolAddress((void**)&wqh,  g_wqh);
    cudaGetSymbolAddress((void**)&wkvh, g_wkvh);
    cudaGetSymbolAddress((void**)&woh,  g_woh);
    cudaGetSymbolAddress((void**)&qh,   g_qh);
    cudaGetSymbolAddress((void**)&kvh,  g_kvh);
    cudaGetSymbolAddress((void**)&yh,   g_yh);

    cudaFuncSetAttribute(f16_gemm_pipe, cudaFuncAttributeMaxDynamicSharedMemorySize, GSMEM);
    cudaFuncSetAttribute(flash_h, cudaFuncAttributeMaxDynamicSharedMemorySize,
                         FLASH_SMEM_BYTES);

    dim3 blk(256);
    const int KVN = 2 * NKV * HD_;   // 512
    // fp32 -> fp16 converts (once); Wk/Wv concatenated into one weight buffer
    cvt16<<<(MROWS * HID_ / 4 + 255) / 256, blk>>>(x,  xh,  MROWS * HID_ / 4);
    cvt16<<<(HID_ * HID_ / 4 + 255) / 256, blk>>>(Wq, wqh, HID_ * HID_ / 4);
    cvt16<<<(NKV * HD_ * HID_ / 4 + 255) / 256, blk>>>(Wk, wkvh, NKV * HD_ * HID_ / 4);
    cvt16<<<(NKV * HD_ * HID_ / 4 + 255) / 256, blk>>>(Wv, wkvh + (size_t)NKV * HD_ * HID_,
                                                       NKV * HD_ * HID_ / 4);
    cvt16<<<(HID_ * HID_ / 4 + 255) / 256, blk>>>(Wo, woh, HID_ * HID_ / 4);

    // Projections (fp16 mma.sync, cp.async pipelined, fp32 accumulate)
    f16_gemm_pipe<<<dim3(HID_ / 128, MROWS / 128), blk, GSMEM>>>(xh, wqh, qh, MROWS, HID_, HID_, 1);
    f16_gemm_pipe<<<dim3(KVN / 128, MROWS / 128), blk, GSMEM>>>(xh, wkvh, kvh, MROWS, KVN, HID_, 1);
    // RoPE + RMSNorm (fp16 in/out, fp32 math)
    rope_rms_h<<<(MROWS * (NH + NKV)) / 8, blk>>>(qh, kvh, cosp, sinp);
    // Flash attention (fp16 mma.sync, BKV=128, cp.async double-buffered KV)
    flash_h<<<dim3(T_ / 128, NH, B_), blk, FLASH_SMEM_BYTES>>>(qh, kvh, yh);
    // Output projection -> fp32 out
    f16_gemm_pipe<<<dim3(HID_ / 128, MROWS / 128), blk, GSMEM>>>(yh, woh, out, MROWS, HID_, HID_, 0);
}